// round 9
// baseline (speedup 1.0000x reference)
#include <cuda_runtime.h>
#include <cuda_bf16.h>
#include <math.h>
#include <stdint.h>

#define Bb   2
#define CIN  64
#define HIDc 128
#define C2   256
#define DDim 32
#define HHe  56
#define WWi  56
#define HW   3136
#define PP   100352

__device__ float g_xz [Bb*(size_t)C2*PP];
__device__ float g_dw [Bb*(size_t)HIDc*PP];          // x1 only
__device__ float g_x1c[Bb*(size_t)HIDc*PP];
__device__ float g_pool[Bb*HIDc*DDim];
__device__ float g_gate[Bb*HIDc*DDim];
// packed bf16 input: [b][cc 8][d][h][ws 58][24ch] as u32 pairs (12 u32 per ws)
__device__ __align__(16) unsigned g_dwPh[(size_t)Bb*8*DDim*HHe*696];
__device__ __align__(16) unsigned g_dwPl[(size_t)Bb*8*DDim*HHe*696];
// packed A-frag weights: [ (kd*3+kh)*8+cc ][kw 3][gmt 8][lane 32][v 4] u32
__device__ __align__(16) unsigned g_wTh[72*3072];
__device__ __align__(16) unsigned g_wTl[72*3072];

__device__ __forceinline__ float sigmoidf_(float x){ return 1.f/(1.f+expf(-x)); }
__device__ __forceinline__ unsigned s2u(const void* p){ unsigned a; asm("{ .reg .u64 t; cvta.to.shared.u64 t, %1; cvt.u32.u64 %0, t; }" : "=r"(a) : "l"(p)); return a; }
__device__ __forceinline__ void bwait(unsigned a, unsigned par){
    asm volatile("{\n\t.reg .pred P;\n\tLW%=:\n\tmbarrier.try_wait.parity.acquire.cta.shared::cta.b64 P, [%0], %1, 0x989680;\n\t@P bra.uni LD%=;\n\tbra.uni LW%=;\n\tLD%=:\n\t}" :: "r"(a), "r"(par) : "memory");
}
__device__ __forceinline__ void bulkcp(unsigned dst, const void* src, unsigned bytes, unsigned mbar){
    asm volatile("cp.async.bulk.shared::cluster.global.mbarrier::complete_tx::bytes [%0], [%1], %2, [%3];"
                 :: "r"(dst), "l"(src), "r"(bytes), "r"(mbar) : "memory");
}
__device__ __forceinline__ void mma16(float* c, const uint4 a, unsigned b0, unsigned b1){
    asm volatile("mma.sync.aligned.m16n8k16.row.col.f32.bf16.bf16.f32 "
                 "{%0,%1,%2,%3}, {%4,%5,%6,%7}, {%8,%9}, {%0,%1,%2,%3};"
                 : "+f"(c[0]), "+f"(c[1]), "+f"(c[2]), "+f"(c[3])
                 : "r"(a.x), "r"(a.y), "r"(a.z), "r"(a.w), "r"(b0), "r"(b1));
}
__device__ __forceinline__ unsigned pack2(float x0, float x1){
    unsigned short u0 = __bfloat16_as_ushort(__float2bfloat16_rn(x0));
    unsigned short u1 = __bfloat16_as_ushort(__float2bfloat16_rn(x1));
    return (unsigned)u0 | ((unsigned)u1 << 16);
}

// ---------------- K1: proj_in ----------------
__global__ __launch_bounds__(256)
void k_proj(const float* __restrict__ inp, const float* __restrict__ W_in){
    extern __shared__ float sw[];
    int tid = threadIdx.x;
    for (int i = tid; i < C2*CIN; i += 256) sw[i] = W_in[i];
    __syncthreads();
    int b = blockIdx.y;
    int p = blockIdx.x*256 + tid;
    float in[CIN];
#pragma unroll
    for (int c = 0; c < CIN; c++) in[c] = inp[(b*CIN + c)*PP + p];
    float* dst = g_xz + (size_t)b*C2*PP + p;
    for (int o = 0; o < C2; o++){
        const float4* wr = (const float4*)(sw + o*CIN);
        float acc = 0.f;
#pragma unroll
        for (int q = 0; q < CIN/4; q++){
            float4 w = wr[q];
            acc += in[4*q]*w.x + in[4*q+1]*w.y + in[4*q+2]*w.z + in[4*q+3]*w.w;
        }
        dst[(size_t)o*PP] = acc;
    }
}

// ---------------- K2: depthwise 3x3x3; store x1, pool x2 ----------------
__global__ __launch_bounds__(256)
void k_dw(const float* __restrict__ W_dw){
    __shared__ float s[3*58*58];
    __shared__ float red[256];
    int bid = blockIdx.x;
    int d = bid & 31, c = (bid >> 5) & 255, b = bid >> 13;
    int tid = threadIdx.x;
    const float* src = g_xz + ((size_t)(b*C2 + c))*PP;
    for (int idx = tid; idx < 3*58*58; idx += 256){
        int ww = idx % 58; int t = idx / 58;
        int hh = t % 58;   int dd = t / 58;
        int gd = d + dd - 1, gh = hh - 1, gw = ww - 1;
        float v = 0.f;
        if ((unsigned)gd < DDim && (unsigned)gh < HHe && (unsigned)gw < WWi)
            v = src[gd*HW + gh*WWi + gw];
        s[idx] = v;
    }
    __syncthreads();
    float wv[27];
#pragma unroll
    for (int t = 0; t < 27; t++) wv[t] = W_dw[c*27 + t];
    float* dst = (c < HIDc) ? (g_dw + ((size_t)(b*HIDc + c))*PP + d*HW) : 0;
    float psum = 0.f;
    for (int idx = tid; idx < HW; idx += 256){
        int h = idx / 56, w = idx % 56;
        float acc = 0.f;
#pragma unroll
        for (int kd = 0; kd < 3; kd++)
#pragma unroll
            for (int kh = 0; kh < 3; kh++)
#pragma unroll
                for (int kw = 0; kw < 3; kw++)
                    acc += s[(kd*58 + h+kh)*58 + (w+kw)] * wv[(kd*3+kh)*3 + kw];
        if (dst) dst[idx] = acc;
        psum += acc;
    }
    if (c >= HIDc){
        red[tid] = psum;
        __syncthreads();
        for (int off = 128; off > 0; off >>= 1){
            if (tid < off) red[tid] += red[tid + off];
            __syncthreads();
        }
        if (tid == 0) g_pool[(b*HIDc + (c - HIDc))*DDim + d] = red[0] * (1.f/HW);
    }
}

// ---------------- K2c: input split-bf16 pack + weight A-frag pack ------------
__global__ __launch_bounds__(256)
void k_cvt(const float* __restrict__ Ws){
    int bid = blockIdx.x, tid = threadIdx.x;
    if (bid < 28672){
        __shared__ float s[16*56];
        int h = bid % 56, d = (bid/56) & 31, cc = (bid/(56*32)) & 7, b = bid/(56*32*8);
        for (int idx = tid; idx < 16*56; idx += 256){
            int ch = idx / 56, w = idx % 56;
            s[idx] = g_dw[((size_t)(b*HIDc + cc*16 + ch))*PP + d*HW + h*56 + w];
        }
        __syncthreads();
        if (tid < 58){
            int ws = tid, w = ws - 1;
            unsigned hu[12], lu[12];
#pragma unroll
            for (int j = 0; j < 12; j++){
                float x0 = 0.f, x1 = 0.f;
                if ((unsigned)w < 56u && j < 8){ x0 = s[(2*j)*56 + w]; x1 = s[(2*j+1)*56 + w]; }
                unsigned hp = pack2(x0, x1);
                __nv_bfloat16 h0 = __ushort_as_bfloat16((unsigned short)hp);
                __nv_bfloat16 h1 = __ushort_as_bfloat16((unsigned short)(hp >> 16));
                lu[j] = pack2(x0 - __bfloat162float(h0), x1 - __bfloat162float(h1));
                hu[j] = hp;
            }
            size_t base = (((size_t)((b*8 + cc)*32 + d))*56 + h)*696 + ws*12;
            uint4* dh = (uint4*)(g_dwPh + base);
            uint4* dl = (uint4*)(g_dwPl + base);
            dh[0] = make_uint4(hu[0],hu[1],hu[2],hu[3]);
            dh[1] = make_uint4(hu[4],hu[5],hu[6],hu[7]);
            dh[2] = make_uint4(hu[8],hu[9],hu[10],hu[11]);
            dl[0] = make_uint4(lu[0],lu[1],lu[2],lu[3]);
            dl[1] = make_uint4(lu[4],lu[5],lu[6],lu[7]);
            dl[2] = make_uint4(lu[8],lu[9],lu[10],lu[11]);
        }
    } else {
        int i = (bid - 28672)*256 + tid;
        if (i >= 72*3072) return;
        int s2 = i / 3072, r = i % 3072;
        int kd = s2 / 24, kh = (s2 / 8) % 3, cc = s2 & 7;
        int kw = r >> 10, gmt = (r >> 7) & 7, lane = (r >> 2) & 31, v = r & 3;
        int o  = gmt*16 + (lane >> 2) + 8*(v & 1);
        int ch = cc*16 + (lane & 3)*2 + 8*(v >> 1);
        int t27 = kd*9 + kh*3 + kw;
        float w0 = Ws[((size_t)o*HIDc + ch)*27 + t27];
        float w1 = Ws[((size_t)o*HIDc + ch + 1)*27 + t27];
        unsigned hp = pack2(w0, w1);
        __nv_bfloat16 h0 = __ushort_as_bfloat16((unsigned short)hp);
        __nv_bfloat16 h1 = __ushort_as_bfloat16((unsigned short)(hp >> 16));
        g_wTh[i] = hp;
        g_wTl[i] = pack2(w0 - __bfloat162float(h0), w1 - __bfloat162float(h1));
    }
}

// ---------------- K3: temporal branch ----------------
__global__ __launch_bounds__(256)
void k_mamba(const float* __restrict__ W_t1, const float* __restrict__ W_t2,
             const float* __restrict__ in_w, const float* __restrict__ conv_w,
             const float* __restrict__ conv_b, const float* __restrict__ x_w,
             const float* __restrict__ dt_w, const float* __restrict__ dt_b,
             const float* __restrict__ A_log, const float* __restrict__ Dp,
             const float* __restrict__ out_w){
    extern __shared__ float sm[];
    float* s_pool = sm;
    float* s_seq  = sm + 4096;
    float* s_xr   = sm + 8192;
    float* s_x    = sm + 16384;
    float* s_z    = sm + 24576;
    float* s_dt   = sm + 32768;
    float* s_proj = sm + 40960;
    int b = blockIdx.x, tid = threadIdx.x;
    for (int i = tid; i < HIDc*DDim; i += 256) s_pool[i] = g_pool[b*HIDc*DDim + i];
    __syncthreads();
    for (int idx = tid; idx < DDim*HIDc; idx += 256){
        int t = idx >> 7, i = idx & 127;
        float a = 0.f;
        const float* w = W_t1 + i*HIDc;
        for (int c = 0; c < HIDc; c++) a += w[c] * s_pool[c*DDim + t];
        s_seq[t*HIDc + i] = a;
    }
    __syncthreads();
    for (int idx = tid; idx < DDim*512; idx += 256){
        int t = idx >> 9, j = idx & 511;
        float a = 0.f;
        const float* w = in_w + j*HIDc;
        const float* u = s_seq + t*HIDc;
        for (int i = 0; i < HIDc; i++) a += u[i]*w[i];
        if (j < 256) s_xr[t*256 + j] = a; else s_z[t*256 + (j-256)] = a;
    }
    __syncthreads();
    for (int idx = tid; idx < DDim*256; idx += 256){
        int t = idx >> 8, j = idx & 255;
        float a = conv_b[j];
#pragma unroll
        for (int k = 0; k < 4; k++){
            int tt = t + k - 3;
            if (tt >= 0) a += s_xr[tt*256 + j] * conv_w[j*4 + k];
        }
        s_x[idx] = a * sigmoidf_(a);
    }
    __syncthreads();
    for (int idx = tid; idx < DDim*40; idx += 256){
        int t = idx / 40, q = idx % 40;
        float a = 0.f;
        const float* w = x_w + q*256;
        const float* u = s_x + t*256;
        for (int j = 0; j < 256; j++) a += u[j]*w[j];
        s_proj[idx] = a;
    }
    __syncthreads();
    for (int idx = tid; idx < DDim*256; idx += 256){
        int t = idx >> 8, j = idx & 255;
        float a = dt_b[j];
#pragma unroll
        for (int r = 0; r < 8; r++) a += s_proj[t*40 + r]*dt_w[j*8 + r];
        s_dt[idx] = (a > 20.f) ? a : log1pf(expf(a));
    }
    __syncthreads();
    {
        int dch = tid;
        float A[16], h[16];
#pragma unroll
        for (int n = 0; n < 16; n++){ A[n] = -expf(A_log[dch*16 + n]); h[n] = 0.f; }
        float Dv = Dp[dch];
        for (int t = 0; t < DDim; t++){
            float dtv = s_dt[t*256 + dch];
            float xv  = s_x [t*256 + dch];
            float y = 0.f;
#pragma unroll
            for (int n = 0; n < 16; n++){
                float dA = expf(dtv * A[n]);
                h[n] = dA*h[n] + dtv * s_proj[t*40 + 8 + n] * xv;
                y += h[n] * s_proj[t*40 + 24 + n];
            }
            y += xv * Dv;
            float zv = s_z[t*256 + dch];
            y *= zv * sigmoidf_(zv);
            s_xr[t*256 + dch] = y;
        }
    }
    __syncthreads();
    for (int idx = tid; idx < DDim*HIDc; idx += 256){
        int t = idx >> 7, o = idx & 127;
        float a = 0.f;
        const float* w = out_w + o*256;
        const float* u = s_xr + t*256;
        for (int j = 0; j < 256; j++) a += u[j]*w[j];
        s_seq[idx] = a;
    }
    __syncthreads();
    for (int idx = tid; idx < DDim*HIDc; idx += 256){
        int t = idx >> 7, o = idx & 127;
        float a = 0.f;
        const float* w = W_t2 + o*HIDc;
        const float* u = s_seq + t*HIDc;
        for (int c = 0; c < HIDc; c++) a += u[c]*w[c];
        g_gate[(b*HIDc + o)*DDim + t] = sigmoidf_(a);
    }
}

// ---------------- K4: bf16-split mma.sync conv 128->128 + ReLU ---------------
// 512 thr = 16 warps (mw 0..3 x nw 0..3). Warp: 32 o x 56 pos (row h0+nw).
// Stage = (kd,kh,cc16): input 4 rows x 58ws x 24ch bf16 hi/lo + A-frag weights.
#define INB  11136              // 4*58*48 bytes per hi (or lo)
#define WBY  12288
#define BUFB (2*INB + 2*WBY)    // 46848
__global__ __launch_bounds__(512)
void k_conv_mma(){
    extern __shared__ __align__(128) char smem[];
    __shared__ __align__(8) unsigned long long mbars[2];
    unsigned usb = s2u(smem);
    unsigned umb = s2u(mbars);
    int tid = threadIdx.x, lane = tid & 31, wid = tid >> 5;
    int lq = lane >> 2, lr = lane & 3;
    int mw = wid >> 2, nw = wid & 3;
    int bid = blockIdx.x;
    int ht = bid % 14, d = (bid/14) & 31, b = bid / (14*32);
    int h0 = ht * 4;

    if (tid == 0){
        asm volatile("mbarrier.init.shared.b64 [%0], 1;" :: "r"(umb) : "memory");
        asm volatile("mbarrier.init.shared.b64 [%0], 1;" :: "r"(umb + 8) : "memory");
    }
    __syncthreads();

    int kdlist[3]; int nk = 0;
#pragma unroll
    for (int kd = 0; kd < 3; kd++){
        int gd = d + kd - 1;
        if (0 <= gd && gd < DDim) kdlist[nk++] = kd;
    }
    int S = nk * 24;

    auto issue = [&](int s){
        int buf = s & 1;
        int cc = s & 7, kh = (s >> 3) % 3, ki = s / 24;
        int kd = kdlist[ki];
        int gd = d + kd - 1;
        int s2 = (kd*3 + kh)*8 + cc;
        if (tid == 0){
            int nv = 0;
#pragma unroll
            for (int r = 0; r < 4; r++){ int gh = h0 + kh - 1 + r; nv += ((unsigned)gh < 56u); }
            unsigned tx = (unsigned)(nv*2*2784 + 2*WBY);
            asm volatile("mbarrier.arrive.expect_tx.shared.b64 _, [%0], %1;"
                         :: "r"(umb + buf*8), "r"(tx) : "memory");
        }
        if (tid < 8){
            int which = tid >> 2, r = tid & 3;
            int gh = h0 + kh - 1 + r;
            if ((unsigned)gh < 56u){
                const unsigned* srcb = (which ? g_dwPl : g_dwPh) +
                    (((size_t)((b*8 + cc)*32 + gd))*56 + gh)*696;
                unsigned dst = usb + (unsigned)(buf*BUFB + which*INB + r*2784);
                bulkcp(dst, srcb, 2784u, umb + buf*8);
            }
        } else if (tid == 8){
            bulkcp(usb + (unsigned)(buf*BUFB + 2*INB), g_wTh + (size_t)s2*3072, 12288u, umb + buf*8);
        } else if (tid == 9){
            bulkcp(usb + (unsigned)(buf*BUFB + 2*INB + WBY), g_wTl + (size_t)s2*3072, 12288u, umb + buf*8);
        }
    };

    float acc[2][7][4];
#pragma unroll
    for (int t = 0; t < 2; t++)
#pragma unroll
        for (int nt = 0; nt < 7; nt++)
#pragma unroll
            for (int j = 0; j < 4; j++) acc[t][nt][j] = 0.f;

    issue(0);
    for (int s = 0; s < S; s++){
        if (s + 1 < S) issue(s + 1);
        bwait(umb + (s&1)*8, (unsigned)((s >> 1) & 1));
        int kh = (s >> 3) % 3;
        const char* buf = smem + (s&1)*BUFB;
        const uint4* wHp = (const uint4*)(buf + 2*INB);
        const uint4* wLp = (const uint4*)(buf + 2*INB + WBY);
        int gh_w = h0 + kh - 1 + nw;
        bool ok = (unsigned)gh_w < 56u;
#pragma unroll
        for (int kw = 0; kw < 3; kw++){
            uint4 Ah[2], Al[2];
#pragma unroll
            for (int t = 0; t < 2; t++){
                int idx = (kw*8 + mw*2 + t)*32 + lane;
                Ah[t] = wHp[idx];
                Al[t] = wLp[idx];
            }
#pragma unroll
            for (int nt = 0; nt < 7; nt++){
                unsigned bh0 = 0, bh1 = 0, bl0 = 0, bl1 = 0;
                if (ok){
                    int ws = nt*8 + lq + kw;
                    const char* bp = buf + (nw*58 + ws)*48 + lr*4;
                    bh0 = *(const unsigned*)(bp);
                    bh1 = *(const unsigned*)(bp + 16);
                    bl0 = *(const unsigned*)(bp + INB);
                    bl1 = *(const unsigned*)(bp + INB + 16);
                }
#pragma unroll
                for (int t = 0; t < 2; t++){
                    mma16(acc[t][nt], Ah[t], bh0, bh1);
                    mma16(acc[t][nt], Ah[t], bl0, bl1);
                    mma16(acc[t][nt], Al[t], bh0, bh1);
                }
            }
        }
        __syncthreads();
    }

    int h = h0 + nw;
#pragma unroll
    for (int t = 0; t < 2; t++){
        int o = (mw*2 + t)*16 + lq;
        float* base0 = g_x1c + ((size_t)(b*HIDc + o))*PP + (size_t)d*HW + h*56;
#pragma unroll
        for (int nt = 0; nt < 7; nt++){
            int w = nt*8 + 2*lr;
            float2 v0, v1;
            v0.x = fmaxf(acc[t][nt][0], 0.f); v0.y = fmaxf(acc[t][nt][1], 0.f);
            v1.x = fmaxf(acc[t][nt][2], 0.f); v1.y = fmaxf(acc[t][nt][3], 0.f);
            *(float2*)(base0 + w) = v0;
            *(float2*)(base0 + (size_t)8*PP + w) = v1;
        }
    }
}

// ---------------- K5: gate + proj_out ----------------
__global__ __launch_bounds__(256)
void k_final(const float* __restrict__ W_out, float* __restrict__ out){
    __shared__ float sw[HIDc*64];
    int tid = threadIdx.x;
    for (int i = tid; i < HIDc*64; i += 256){
        int c = i >> 6, o = i & 63;
        sw[i] = W_out[o*HIDc + c];
    }
    __syncthreads();
    int b = blockIdx.y;
    int p = blockIdx.x*256 + tid;
    int d = p / HW;
    float acc[64];
#pragma unroll
    for (int o = 0; o < 64; o++) acc[o] = 0.f;
    const float* src  = g_x1c + (size_t)b*HIDc*PP + p;
    const float* gate = g_gate + b*HIDc*DDim + d;
    for (int c = 0; c < HIDc; c++){
        float v = src[(size_t)c*PP] * gate[c*DDim];
        const float4* wr = (const float4*)(sw + c*64);
#pragma unroll
        for (int q = 0; q < 16; q++){
            float4 w = wr[q];
            acc[4*q]   += v*w.x;
            acc[4*q+1] += v*w.y;
            acc[4*q+2] += v*w.z;
            acc[4*q+3] += v*w.w;
        }
    }
    float* dst = out + (size_t)b*64*PP + p;
#pragma unroll
    for (int o = 0; o < 64; o++) dst[(size_t)o*PP] = acc[o];
}

// ---------------- launch ----------------
extern "C" void kernel_launch(void* const* d_in, const int* in_sizes, int n_in,
                              void* d_out, int out_size){
    const float* inp      = (const float*)d_in[0];
    const float* W_in     = (const float*)d_in[1];
    const float* W_dw     = (const float*)d_in[2];
    const float* W_s      = (const float*)d_in[3];
    const float* W_t1     = (const float*)d_in[4];
    const float* W_t2     = (const float*)d_in[5];
    const float* m_in_w   = (const float*)d_in[6];
    const float* m_conv_w = (const float*)d_in[7];
    const float* m_conv_b = (const float*)d_in[8];
    const float* m_x_w    = (const float*)d_in[9];
    const float* m_dt_w   = (const float*)d_in[10];
    const float* m_dt_b   = (const float*)d_in[11];
    const float* m_A_log  = (const float*)d_in[12];
    const float* m_D      = (const float*)d_in[13];
    const float* m_out_w  = (const float*)d_in[14];
    const float* W_out    = (const float*)d_in[15];
    float* out = (float*)d_out;

    cudaFuncSetAttribute(k_proj,     cudaFuncAttributeMaxDynamicSharedMemorySize, C2*CIN*4);
    cudaFuncSetAttribute(k_mamba,    cudaFuncAttributeMaxDynamicSharedMemorySize, 42240*4);
    cudaFuncSetAttribute(k_conv_mma, cudaFuncAttributeMaxDynamicSharedMemorySize, 2*BUFB);

    k_proj    <<<dim3(PP/256, Bb), 256, C2*CIN*4>>>(inp, W_in);          // idx 0
    k_dw      <<<Bb*C2*DDim, 256>>>(W_dw);                               // idx 1
    k_cvt     <<<28672 + 864, 256>>>(W_s);                               // idx 2
    k_conv_mma<<<Bb*DDim*14, 512, 2*BUFB>>>();                           // idx 3 (ncu slot)
    k_mamba   <<<Bb, 256, 42240*4>>>(W_t1, W_t2, m_in_w, m_conv_w, m_conv_b,
                                     m_x_w, m_dt_w, m_dt_b, m_A_log, m_D, m_out_w);
    k_final   <<<dim3(PP/256, Bb), 256>>>(W_out, out);
}

// round 10
// speedup vs baseline: 2.5148x; 2.5148x over previous
#include <cuda_runtime.h>
#include <cuda_fp16.h>
#include <math.h>
#include <stdint.h>

#define Bb   2
#define CIN  64
#define HIDc 128
#define C2   256
#define DDim 32
#define HHe  56
#define WWi  56
#define HW   3136
#define PP   100352

__device__ float g_xz [Bb*(size_t)C2*PP];
__device__ float g_x1c[Bb*(size_t)HIDc*PP];
__device__ float g_pool[Bb*HIDc*DDim];
__device__ float g_gate[Bb*HIDc*DDim];
// depthwise x1 as fp16, interleaved layout [b][d][h][c2 64][w 56] u32 (=u16 pairs along c)
__device__ __align__(16) unsigned short g_dwP[(size_t)Bb*DDim*HHe*7168];
// fp16 A-frag packed conv weights: [s2 72][kw 3][mt 8][lane 32][v 4] u32
__device__ __align__(16) unsigned g_wTh[72*3072];
// mamba intermediates
__device__ float g_seq[Bb*DDim*HIDc];
__device__ float g_xr [Bb*DDim*256];
__device__ float g_z  [Bb*DDim*256];
__device__ float g_y  [Bb*DDim*256];

__device__ __forceinline__ float sigmoidf_(float x){ return 1.f/(1.f+expf(-x)); }
__device__ __forceinline__ unsigned s2u(const void* p){ unsigned a; asm("{ .reg .u64 t; cvta.to.shared.u64 t, %1; cvt.u32.u64 %0, t; }" : "=r"(a) : "l"(p)); return a; }
__device__ __forceinline__ void bwait(unsigned a, unsigned par){
    asm volatile("{\n\t.reg .pred P;\n\tLW%=:\n\tmbarrier.try_wait.parity.acquire.cta.shared::cta.b64 P, [%0], %1, 0x989680;\n\t@P bra.uni LD%=;\n\tbra.uni LW%=;\n\tLD%=:\n\t}" :: "r"(a), "r"(par) : "memory");
}
__device__ __forceinline__ void bulkcp(unsigned dst, const void* src, unsigned bytes, unsigned mbar){
    asm volatile("cp.async.bulk.shared::cluster.global.mbarrier::complete_tx::bytes [%0], [%1], %2, [%3];"
                 :: "r"(dst), "l"(src), "r"(bytes), "r"(mbar) : "memory");
}
__device__ __forceinline__ void mma16f(float* c, const uint4 a, unsigned b0, unsigned b1){
    asm volatile("mma.sync.aligned.m16n8k16.row.col.f32.f16.f16.f32 "
                 "{%0,%1,%2,%3}, {%4,%5,%6,%7}, {%8,%9}, {%0,%1,%2,%3};"
                 : "+f"(c[0]), "+f"(c[1]), "+f"(c[2]), "+f"(c[3])
                 : "r"(a.x), "r"(a.y), "r"(a.z), "r"(a.w), "r"(b0), "r"(b1));
}

// ---------------- K1: proj_in ----------------
__global__ __launch_bounds__(256)
void k_proj(const float* __restrict__ inp, const float* __restrict__ W_in){
    extern __shared__ float sw[];
    int tid = threadIdx.x;
    for (int i = tid; i < C2*CIN; i += 256) sw[i] = W_in[i];
    __syncthreads();
    int b = blockIdx.y;
    int p = blockIdx.x*256 + tid;
    float in[CIN];
#pragma unroll
    for (int c = 0; c < CIN; c++) in[c] = inp[(b*CIN + c)*PP + p];
    float* dst = g_xz + (size_t)b*C2*PP + p;
    for (int o = 0; o < C2; o++){
        const float4* wr = (const float4*)(sw + o*CIN);
        float acc = 0.f;
#pragma unroll
        for (int q = 0; q < CIN/4; q++){
            float4 w = wr[q];
            acc += in[4*q]*w.x + in[4*q+1]*w.y + in[4*q+2]*w.z + in[4*q+3]*w.w;
        }
        dst[(size_t)o*PP] = acc;
    }
}

// ---------------- K2: depthwise 3x3x3; x1 -> fp16 interleaved, x2 -> pool ----
__global__ __launch_bounds__(256)
void k_dw(const float* __restrict__ W_dw){
    __shared__ float s[3*58*58];
    __shared__ float red[256];
    int bid = blockIdx.x;
    int d = bid & 31, c = (bid >> 5) & 255, b = bid >> 13;
    int tid = threadIdx.x;
    const float* src = g_xz + ((size_t)(b*C2 + c))*PP;
    for (int idx = tid; idx < 3*58*58; idx += 256){
        int ww = idx % 58; int t = idx / 58;
        int hh = t % 58;   int dd = t / 58;
        int gd = d + dd - 1, gh = hh - 1, gw = ww - 1;
        float v = 0.f;
        if ((unsigned)gd < DDim && (unsigned)gh < HHe && (unsigned)gw < WWi)
            v = src[gd*HW + gh*WWi + gw];
        s[idx] = v;
    }
    __syncthreads();
    float wv[27];
#pragma unroll
    for (int t = 0; t < 27; t++) wv[t] = W_dw[c*27 + t];
    float psum = 0.f;
    size_t Hbase = (size_t)(b*DDim + d)*HHe*7168;
    int coff = (c >> 1)*112 + (c & 1);
    for (int idx = tid; idx < HW; idx += 256){
        int h = idx / 56, w = idx % 56;
        float acc = 0.f;
#pragma unroll
        for (int kd = 0; kd < 3; kd++)
#pragma unroll
            for (int kh = 0; kh < 3; kh++)
#pragma unroll
                for (int kw = 0; kw < 3; kw++)
                    acc += s[(kd*58 + h+kh)*58 + (w+kw)] * wv[(kd*3+kh)*3 + kw];
        if (c < HIDc)
            g_dwP[Hbase + (size_t)h*7168 + coff + 2*w] = __half_as_ushort(__float2half_rn(acc));
        psum += acc;
    }
    if (c >= HIDc){
        red[tid] = psum;
        __syncthreads();
        for (int off = 128; off > 0; off >>= 1){
            if (tid < off) red[tid] += red[tid + off];
            __syncthreads();
        }
        if (tid == 0) g_pool[(b*HIDc + (c - HIDc))*DDim + d] = red[0] * (1.f/HW);
    }
}

// ---------------- K2c: conv weights -> fp16 A-frag pack ----------------
__global__ __launch_bounds__(256)
void k_wt(const float* __restrict__ Ws){
    int i = blockIdx.x*256 + threadIdx.x;
    if (i >= 72*3072) return;
    int v = i & 3, lane = (i >> 2) & 31, mt = (i >> 7) & 7, kw = (i >> 10) % 3, s2 = i / 3072;
    int kd = s2 / 24, kh = (s2 >> 3) % 3, cc = s2 & 7;
    int lq = lane >> 2, lr = lane & 3;
    int o  = mt*16 + lq + 8*(v & 1);
    int c0 = cc*16 + 2*lr + 8*(v >> 1);
    int t27 = kd*9 + kh*3 + kw;
    float w0 = Ws[((size_t)o*HIDc + c0)*27 + t27];
    float w1 = Ws[((size_t)o*HIDc + c0 + 1)*27 + t27];
    __half2 h = __floats2half2_rn(w0, w1);
    g_wTh[i] = *(unsigned*)&h;
}

// ---------------- mamba chain ----------------
__global__ __launch_bounds__(256)
void k_m1(const float* __restrict__ W_t1){          // grid 32
    int idx = blockIdx.x*256 + threadIdx.x;          // (b,t,i): 8192
    int i = idx & 127, t = (idx >> 7) & 31, b = idx >> 12;
    const float* w  = W_t1 + i*HIDc;
    const float* pl = g_pool + b*HIDc*DDim + t;
    float a = 0.f;
    for (int c = 0; c < HIDc; c++) a += w[c] * pl[c*DDim];
    g_seq[idx] = a;
}

__global__ __launch_bounds__(256)
void k_m2(const float* __restrict__ in_w){          // grid 128
    __shared__ float s[HIDc];
    int blk = blockIdx.x, tid = threadIdx.x;
    int half = blk & 1, t = (blk >> 1) & 31, b = blk >> 6;
    if (tid < HIDc) s[tid] = g_seq[(b*DDim + t)*HIDc + tid];
    __syncthreads();
    int j = half*256 + tid;
    const float* w = in_w + (size_t)j*HIDc;
    float a = 0.f;
#pragma unroll 4
    for (int i = 0; i < HIDc; i++) a += s[i]*w[i];
    if (half == 0) g_xr[(b*DDim + t)*256 + tid] = a;
    else           g_z [(b*DDim + t)*256 + tid] = a;
}

__global__ __launch_bounds__(256)
void k_m3(const float* __restrict__ conv_w, const float* __restrict__ conv_b,
          const float* __restrict__ x_w, const float* __restrict__ dt_w,
          const float* __restrict__ dt_b, const float* __restrict__ A_log,
          const float* __restrict__ Dp){            // grid 2
    extern __shared__ float sm[];
    float* s_x    = sm;              // 8192
    float* s_proj = sm + 8192;       // 1280
    float* s_u    = sm + 9472;       // 10240 (x_w, then dt)
    int b = blockIdx.x, tid = threadIdx.x;
    for (int i = tid; i < 40*256; i += 256) s_u[i] = x_w[i];
    __syncthreads();
    for (int idx = tid; idx < DDim*256; idx += 256){
        int t = idx >> 8, j = idx & 255;
        float a = conv_b[j];
#pragma unroll
        for (int k = 0; k < 4; k++){
            int tt = t + k - 3;
            if (tt >= 0) a += g_xr[(b*DDim + tt)*256 + j] * conv_w[j*4 + k];
        }
        s_x[idx] = a * sigmoidf_(a);
    }
    __syncthreads();
    for (int idx = tid; idx < DDim*40; idx += 256){
        int t = idx / 40, q = idx % 40;
        float a = 0.f;
        const float* u = s_x + t*256;
        const float* w = s_u + q*256;
        for (int j = 0; j < 256; j++) a += u[j]*w[j];
        s_proj[idx] = a;
    }
    __syncthreads();
    for (int idx = tid; idx < DDim*256; idx += 256){
        int t = idx >> 8, j = idx & 255;
        float a = dt_b[j];
#pragma unroll
        for (int r = 0; r < 8; r++) a += s_proj[t*40 + r]*dt_w[j*8 + r];
        s_u[idx] = (a > 20.f) ? a : log1pf(expf(a));
    }
    __syncthreads();
    {
        int dch = tid;
        float A[16], h[16];
#pragma unroll
        for (int n = 0; n < 16; n++){ A[n] = -expf(A_log[dch*16 + n]); h[n] = 0.f; }
        float Dv = Dp[dch];
        for (int t = 0; t < DDim; t++){
            float dtv = s_u[t*256 + dch];
            float xv  = s_x[t*256 + dch];
            float y = 0.f;
#pragma unroll
            for (int n = 0; n < 16; n++){
                float dA = expf(dtv * A[n]);
                h[n] = dA*h[n] + dtv * s_proj[t*40 + 8 + n] * xv;
                y += h[n] * s_proj[t*40 + 24 + n];
            }
            y += xv * Dv;
            float zv = g_z[(b*DDim + t)*256 + dch];
            y *= zv * sigmoidf_(zv);
            g_y[(b*DDim + t)*256 + dch] = y;
        }
    }
}

__global__ __launch_bounds__(128)
void k_m4(const float* __restrict__ out_w, const float* __restrict__ W_t2){  // grid 64
    __shared__ float sy[256];
    __shared__ float som[HIDc];
    int bt = blockIdx.x, tid = threadIdx.x;
    int b = bt >> 5, t = bt & 31;
    sy[tid]       = g_y[bt*256 + tid];
    sy[tid + 128] = g_y[bt*256 + 128 + tid];
    __syncthreads();
    {
        const float* w = out_w + (size_t)tid*256;
        float a = 0.f;
#pragma unroll 4
        for (int j = 0; j < 256; j++) a += sy[j]*w[j];
        som[tid] = a;
    }
    __syncthreads();
    {
        const float* w = W_t2 + (size_t)tid*HIDc;
        float a = 0.f;
#pragma unroll 4
        for (int c = 0; c < HIDc; c++) a += som[c]*w[c];
        g_gate[(b*HIDc + tid)*DDim + t] = sigmoidf_(a);
    }
}

// ---------------- K4: fp16 mma.sync conv 128->128 + ReLU ---------------------
// 512 thr = 16 warps (4 mw x 4 nw). Warp: 32 o x 56 pos (out row h0+nw).
// Stage = (kd,kh,cc16): buf = [weights 12288B][input 4 rows x 1792B][pad]
#define INBOFF 12288
#define BUFB   19584
__global__ __launch_bounds__(512)
void k_conv_mma(){
    extern __shared__ __align__(128) char smem[];
    __shared__ __align__(8) unsigned long long mbars[2];
    unsigned usb = s2u(smem);
    unsigned umb = s2u(mbars);
    int tid = threadIdx.x, lane = tid & 31, wid = tid >> 5;
    int lq = lane >> 2, lr = lane & 3;
    int mw = wid >> 2, nw = wid & 3;
    int bid = blockIdx.x;
    int ht = bid % 14, d = (bid/14) & 31, b = bid / (14*32);
    int h0 = ht * 4;

    if (tid == 0){
        asm volatile("mbarrier.init.shared.b64 [%0], 1;" :: "r"(umb) : "memory");
        asm volatile("mbarrier.init.shared.b64 [%0], 1;" :: "r"(umb + 8) : "memory");
    }
    __syncthreads();

    int kdlist[3]; int nk = 0;
#pragma unroll
    for (int kd = 0; kd < 3; kd++){
        int gd = d + kd - 1;
        if (0 <= gd && gd < DDim) kdlist[nk++] = kd;
    }
    int S = nk * 24;

    auto issue = [&](int s){
        int buf = s & 1;
        int cc = s & 7, kh = (s >> 3) % 3, kd = kdlist[s / 24];
        int gd = d + kd - 1;
        int s2 = (kd*3 + kh)*8 + cc;
        if (tid == 0){
            int nv = 0;
#pragma unroll
            for (int r = 0; r < 4; r++){ int gh = h0 + kh - 1 + r; nv += ((unsigned)gh < 56u); }
            unsigned tx = (unsigned)(nv*1792 + 12288);
            asm volatile("mbarrier.arrive.expect_tx.shared.b64 _, [%0], %1;"
                         :: "r"(umb + buf*8), "r"(tx) : "memory");
        }
        if (tid < 4){
            int r = tid, gh = h0 + kh - 1 + r;
            if ((unsigned)gh < 56u){
                const unsigned short* src = g_dwP + (size_t)((b*DDim + gd)*HHe + gh)*7168 + cc*896;
                bulkcp(usb + (unsigned)(buf*BUFB + INBOFF + r*1792), src, 1792u, umb + buf*8);
            }
        } else if (tid == 4){
            bulkcp(usb + (unsigned)(buf*BUFB), g_wTh + (size_t)s2*3072, 12288u, umb + buf*8);
        }
    };

    float acc[2][7][4];
#pragma unroll
    for (int t = 0; t < 2; t++)
#pragma unroll
        for (int nt = 0; nt < 7; nt++)
#pragma unroll
            for (int j = 0; j < 4; j++) acc[t][nt][j] = 0.f;

    issue(0);
    for (int s = 0; s < S; s++){
        if (s + 1 < S) issue(s + 1);
        bwait(umb + (s&1)*8, (unsigned)((s >> 1) & 1));
        int kh = (s >> 3) % 3;
        const char* buf = smem + (s&1)*BUFB;
        const uint4* wp = (const uint4*)buf;
        const unsigned* ib = (const unsigned*)(buf + INBOFF);
        bool okh = (unsigned)(h0 + kh - 1 + nw) < 56u;
#pragma unroll
        for (int kw = 0; kw < 3; kw++){
            uint4 A0 = wp[(kw*8 + mw*2    )*32 + lane];
            uint4 A1 = wp[(kw*8 + mw*2 + 1)*32 + lane];
#pragma unroll
            for (int nt = 0; nt < 7; nt++){
                int w = nt*8 + lq + kw - 1;
                bool ok = okh && ((unsigned)w < 56u);
                int wc = ok ? w : 0;
                unsigned b0 = 0, b1 = 0;
                if (ok){
                    b0 = ib[(nw*8 + lr    )*56 + wc];
                    b1 = ib[(nw*8 + lr + 4)*56 + wc];
                }
                mma16f(acc[0][nt], A0, b0, b1);
                mma16f(acc[1][nt], A1, b0, b1);
            }
        }
        __syncthreads();
    }

    int h = h0 + nw;
#pragma unroll
    for (int t = 0; t < 2; t++){
        int o = (mw*2 + t)*16 + lq;
        float* base0 = g_x1c + ((size_t)(b*HIDc + o))*PP + (size_t)d*HW + h*56;
#pragma unroll
        for (int nt = 0; nt < 7; nt++){
            int w = nt*8 + 2*lr;
            float2 v0, v1;
            v0.x = fmaxf(acc[t][nt][0], 0.f); v0.y = fmaxf(acc[t][nt][1], 0.f);
            v1.x = fmaxf(acc[t][nt][2], 0.f); v1.y = fmaxf(acc[t][nt][3], 0.f);
            *(float2*)(base0 + w) = v0;
            *(float2*)(base0 + (size_t)8*PP + w) = v1;
        }
    }
}

// ---------------- K5: gate + proj_out ----------------
__global__ __launch_bounds__(256)
void k_final(const float* __restrict__ W_out, float* __restrict__ out){
    __shared__ float sw[HIDc*64];
    int tid = threadIdx.x;
    for (int i = tid; i < HIDc*64; i += 256){
        int c = i >> 6, o = i & 63;
        sw[i] = W_out[o*HIDc + c];
    }
    __syncthreads();
    int b = blockIdx.y;
    int p = blockIdx.x*256 + tid;
    int d = p / HW;
    float acc[64];
#pragma unroll
    for (int o = 0; o < 64; o++) acc[o] = 0.f;
    const float* src  = g_x1c + (size_t)b*HIDc*PP + p;
    const float* gate = g_gate + b*HIDc*DDim + d;
    for (int c = 0; c < HIDc; c++){
        float v = src[(size_t)c*PP] * gate[c*DDim];
        const float4* wr = (const float4*)(sw + c*64);
#pragma unroll
        for (int q = 0; q < 16; q++){
            float4 w = wr[q];
            acc[4*q]   += v*w.x;
            acc[4*q+1] += v*w.y;
            acc[4*q+2] += v*w.z;
            acc[4*q+3] += v*w.w;
        }
    }
    float* dst = out + (size_t)b*64*PP + p;
#pragma unroll
    for (int o = 0; o < 64; o++) dst[(size_t)o*PP] = acc[o];
}

// ---------------- launch ----------------
extern "C" void kernel_launch(void* const* d_in, const int* in_sizes, int n_in,
                              void* d_out, int out_size){
    const float* inp      = (const float*)d_in[0];
    const float* W_in     = (const float*)d_in[1];
    const float* W_dw     = (const float*)d_in[2];
    const float* W_s      = (const float*)d_in[3];
    const float* W_t1     = (const float*)d_in[4];
    const float* W_t2     = (const float*)d_in[5];
    const float* m_in_w   = (const float*)d_in[6];
    const float* m_conv_w = (const float*)d_in[7];
    const float* m_conv_b = (const float*)d_in[8];
    const float* m_x_w    = (const float*)d_in[9];
    const float* m_dt_w   = (const float*)d_in[10];
    const float* m_dt_b   = (const float*)d_in[11];
    const float* m_A_log  = (const float*)d_in[12];
    const float* m_D      = (const float*)d_in[13];
    const float* m_out_w  = (const float*)d_in[14];
    const float* W_out    = (const float*)d_in[15];
    float* out = (float*)d_out;

    cudaFuncSetAttribute(k_proj, cudaFuncAttributeMaxDynamicSharedMemorySize, C2*CIN*4);
    cudaFuncSetAttribute(k_m3,   cudaFuncAttributeMaxDynamicSharedMemorySize, 19712*4);
    cudaFuncSetAttribute(k_conv_mma, cudaFuncAttributeMaxDynamicSharedMemorySize, 2*BUFB);

    k_proj    <<<dim3(PP/256, Bb), 256, C2*CIN*4>>>(inp, W_in);   // idx 0
    k_dw      <<<Bb*C2*DDim, 256>>>(W_dw);                        // idx 1
    k_wt      <<<864, 256>>>(W_s);                                // idx 2
    k_conv_mma<<<Bb*DDim*14, 512, 2*BUFB>>>();                    // idx 3 (ncu slot)
    k_m1      <<<32, 256>>>(W_t1);
    k_m2      <<<128, 256>>>(m_in_w);
    k_m3      <<<Bb, 256, 19712*4>>>(m_conv_w, m_conv_b, m_x_w, m_dt_w,
                                     m_dt_b, m_A_log, m_D);
    k_m4      <<<64, 128>>>(m_out_w, W_t2);
    k_final   <<<dim3(PP/256, Bb), 256>>>(W_out, out);
}

// round 11
// speedup vs baseline: 3.2081x; 1.2757x over previous
#include <cuda_runtime.h>
#include <cuda_fp16.h>
#include <math.h>
#include <stdint.h>

#define Bb   2
#define CIN  64
#define HIDc 128
#define C2   256
#define DDim 32
#define HHe  56
#define WWi  56
#define HW   3136
#define PP   100352

__device__ float g_xz [Bb*(size_t)C2*PP];
__device__ float g_x1c[Bb*(size_t)HIDc*PP];
__device__ float g_pool[Bb*HIDc*DDim];
__device__ float g_gate[Bb*HIDc*DDim];
// fully halo-padded fp16 x1: [b][dp 34][hp 60][cc 8][c2 8][ws 72] u32-pairs; pads stay zero (CUDA zero-init)
__device__ __align__(16) unsigned short g_dwP[(size_t)Bb*34*60*64*72*2];
// fp16 A-frag packed conv weights: [s 72][kw 3][mt 8][lane 32][v 4] u32
__device__ __align__(16) unsigned g_wTh[72*3072];
// fp16 A-frag packed W_in: [ks 4][mt 16][lane 32][v 4] u32
__device__ __align__(16) unsigned g_pA[8192];
// mamba intermediates
__device__ float g_seq[Bb*DDim*HIDc];
__device__ float g_xr [Bb*DDim*256];
__device__ float g_z  [Bb*DDim*256];
__device__ float g_y  [Bb*DDim*256];

__device__ __forceinline__ float sigmoidf_(float x){ return 1.f/(1.f+expf(-x)); }
__device__ __forceinline__ unsigned s2u(const void* p){ unsigned a; asm("{ .reg .u64 t; cvta.to.shared.u64 t, %1; cvt.u32.u64 %0, t; }" : "=r"(a) : "l"(p)); return a; }
__device__ __forceinline__ void bwait(unsigned a, unsigned par){
    asm volatile("{\n\t.reg .pred P;\n\tLW%=:\n\tmbarrier.try_wait.parity.acquire.cta.shared::cta.b64 P, [%0], %1, 0x989680;\n\t@P bra.uni LD%=;\n\tbra.uni LW%=;\n\tLD%=:\n\t}" :: "r"(a), "r"(par) : "memory");
}
__device__ __forceinline__ void bulkcp(unsigned dst, const void* src, unsigned bytes, unsigned mbar){
    asm volatile("cp.async.bulk.shared::cluster.global.mbarrier::complete_tx::bytes [%0], [%1], %2, [%3];"
                 :: "r"(dst), "l"(src), "r"(bytes), "r"(mbar) : "memory");
}
__device__ __forceinline__ void mma16f(float* c, const uint4 a, unsigned b0, unsigned b1){
    asm volatile("mma.sync.aligned.m16n8k16.row.col.f32.f16.f16.f32 "
                 "{%0,%1,%2,%3}, {%4,%5,%6,%7}, {%8,%9}, {%0,%1,%2,%3};"
                 : "+f"(c[0]), "+f"(c[1]), "+f"(c[2]), "+f"(c[3])
                 : "r"(a.x), "r"(a.y), "r"(a.z), "r"(a.w), "r"(b0), "r"(b1));
}

// ---------------- K0: W_in A-frag pack ----------------
__global__ __launch_bounds__(256)
void k_wtp(const float* __restrict__ W_in){
    int i = blockIdx.x*256 + threadIdx.x;
    if (i >= 8192) return;
    int v = i & 3, lane = (i >> 2) & 31, mt = (i >> 7) & 15, ks = i >> 11;
    int o = mt*16 + (lane >> 2) + 8*(v & 1);
    int c = ks*16 + 2*(lane & 3) + 8*(v >> 1);
    __half2 h = __floats2half2_rn(W_in[o*CIN + c], W_in[o*CIN + c + 1]);
    g_pA[i] = *(unsigned*)&h;
}

// ---------------- K1: proj_in via fp16 mma ----------------
__global__ __launch_bounds__(512)
void k_projT(const float* __restrict__ inp){
    extern __shared__ unsigned ps[];          // A 8192 u32 | B 4608 u32
    unsigned* sB = ps + 8192;
    uint4* sA4 = (uint4*)ps;
    int tid = threadIdx.x, lane = tid & 31, wid = tid >> 5;
    int lq = lane >> 2, lr = lane & 3;
    int mw = wid >> 2, nw = wid & 3;
    int b = blockIdx.y, p0 = blockIdx.x*128;
    const uint4* gA = (const uint4*)g_pA;
    for (int i = tid; i < 2048; i += 512) sA4[i] = gA[i];
    for (int i = tid; i < 4096; i += 512){
        int c2 = i >> 7, p = i & 127;
        float x0 = inp[((size_t)(b*CIN + 2*c2))*PP + p0 + p];
        float x1 = inp[((size_t)(b*CIN + 2*c2 + 1))*PP + p0 + p];
        __half2 h = __floats2half2_rn(x0, x1);
        sB[p*36 + c2] = *(unsigned*)&h;
    }
    __syncthreads();
    float acc[4][4][4];
#pragma unroll
    for (int t = 0; t < 4; t++)
#pragma unroll
        for (int nt = 0; nt < 4; nt++)
#pragma unroll
            for (int j = 0; j < 4; j++) acc[t][nt][j] = 0.f;
#pragma unroll
    for (int ks = 0; ks < 4; ks++){
        uint4 A[4];
#pragma unroll
        for (int t = 0; t < 4; t++) A[t] = sA4[(ks*16 + mw*4 + t)*32 + lane];
#pragma unroll
        for (int nt = 0; nt < 4; nt++){
            int pr = nw*32 + nt*8 + lq;
            unsigned b0 = sB[pr*36 + ks*8 + lr];
            unsigned b1 = sB[pr*36 + ks*8 + lr + 4];
#pragma unroll
            for (int t = 0; t < 4; t++) mma16f(acc[t][nt], A[t], b0, b1);
        }
    }
#pragma unroll
    for (int t = 0; t < 4; t++){
        int o = mw*64 + t*16 + lq;
        float* d0 = g_xz + ((size_t)(b*C2 + o))*PP + p0 + nw*32 + 2*lr;
#pragma unroll
        for (int nt = 0; nt < 4; nt++){
            float2 v0, v1;
            v0.x = acc[t][nt][0]; v0.y = acc[t][nt][1];
            v1.x = acc[t][nt][2]; v1.y = acc[t][nt][3];
            *(float2*)(d0 + nt*8) = v0;
            *(float2*)(d0 + (size_t)8*PP + nt*8) = v1;
        }
    }
}

// ---------------- K2: depthwise 3x3x3; x1 -> padded fp16, x2 -> pool ---------
__global__ __launch_bounds__(256)
void k_dw(const float* __restrict__ W_dw){
    __shared__ float s[3*58*58];
    __shared__ float red[256];
    int bid = blockIdx.x;
    int d = bid & 31, c = (bid >> 5) & 255, b = bid >> 13;
    int tid = threadIdx.x;
    const float* src = g_xz + ((size_t)(b*C2 + c))*PP;
    for (int idx = tid; idx < 3*58*58; idx += 256){
        int ww = idx % 58; int t = idx / 58;
        int hh = t % 58;   int dd = t / 58;
        int gd = d + dd - 1, gh = hh - 1, gw = ww - 1;
        float v = 0.f;
        if ((unsigned)gd < DDim && (unsigned)gh < HHe && (unsigned)gw < WWi)
            v = src[gd*HW + gh*WWi + gw];
        s[idx] = v;
    }
    __syncthreads();
    float wv[27];
#pragma unroll
    for (int t = 0; t < 27; t++) wv[t] = W_dw[c*27 + t];
    float psum = 0.f;
    // padded layout: u16 idx = (((dpl*60 + h+1)*64 + cidx)*72 + w+1)*2 + (c&1)
    size_t plane = (size_t)((b*34 + d + 1)*60);
    int cidx = (c >> 4)*8 + ((c >> 1) & 7);
    for (int idx = tid; idx < HW; idx += 256){
        int h = idx / 56, w = idx % 56;
        float acc = 0.f;
#pragma unroll
        for (int kd = 0; kd < 3; kd++)
#pragma unroll
            for (int kh = 0; kh < 3; kh++)
#pragma unroll
                for (int kw = 0; kw < 3; kw++)
                    acc += s[(kd*58 + h+kh)*58 + (w+kw)] * wv[(kd*3+kh)*3 + kw];
        if (c < HIDc)
            g_dwP[(((plane + h + 1)*64 + cidx)*72 + w + 1)*2 + (c & 1)] =
                __half_as_ushort(__float2half_rn(acc));
        psum += acc;
    }
    if (c >= HIDc){
        red[tid] = psum;
        __syncthreads();
        for (int off = 128; off > 0; off >>= 1){
            if (tid < off) red[tid] += red[tid + off];
            __syncthreads();
        }
        if (tid == 0) g_pool[(b*HIDc + (c - HIDc))*DDim + d] = red[0] * (1.f/HW);
    }
}

// ---------------- K2c: conv weights -> fp16 A-frag pack ----------------
__global__ __launch_bounds__(256)
void k_wt(const float* __restrict__ Ws){
    int i = blockIdx.x*256 + threadIdx.x;
    if (i >= 72*3072) return;
    int v = i & 3, lane = (i >> 2) & 31, mt = (i >> 7) & 7, kw = (i >> 10) % 3, s2 = i / 3072;
    int kd = s2 / 24, kh = (s2 >> 3) % 3, cc = s2 & 7;
    int lq = lane >> 2, lr = lane & 3;
    int o  = mt*16 + lq + 8*(v & 1);
    int c0 = cc*16 + 2*lr + 8*(v >> 1);
    int t27 = kd*9 + kh*3 + kw;
    __half2 h = __floats2half2_rn(Ws[((size_t)o*HIDc + c0)*27 + t27],
                                  Ws[((size_t)o*HIDc + c0 + 1)*27 + t27]);
    g_wTh[i] = *(unsigned*)&h;
}

// ---------------- mamba chain ----------------
__global__ __launch_bounds__(256)
void k_m1(const float* __restrict__ W_t1){
    int idx = blockIdx.x*256 + threadIdx.x;
    int i = idx & 127, t = (idx >> 7) & 31, b = idx >> 12;
    const float* w  = W_t1 + i*HIDc;
    const float* pl = g_pool + b*HIDc*DDim + t;
    float a = 0.f;
    for (int c = 0; c < HIDc; c++) a += w[c] * pl[c*DDim];
    g_seq[idx] = a;
}

__global__ __launch_bounds__(256)
void k_m2(const float* __restrict__ in_w){
    __shared__ float s[HIDc];
    int blk = blockIdx.x, tid = threadIdx.x;
    int half = blk & 1, t = (blk >> 1) & 31, b = blk >> 6;
    if (tid < HIDc) s[tid] = g_seq[(b*DDim + t)*HIDc + tid];
    __syncthreads();
    int j = half*256 + tid;
    const float* w = in_w + (size_t)j*HIDc;
    float a = 0.f;
#pragma unroll 4
    for (int i = 0; i < HIDc; i++) a += s[i]*w[i];
    if (half == 0) g_xr[(b*DDim + t)*256 + tid] = a;
    else           g_z [(b*DDim + t)*256 + tid] = a;
}

__global__ __launch_bounds__(256)
void k_m3(const float* __restrict__ conv_w, const float* __restrict__ conv_b,
          const float* __restrict__ x_w, const float* __restrict__ dt_w,
          const float* __restrict__ dt_b, const float* __restrict__ A_log,
          const float* __restrict__ Dp){
    extern __shared__ float sm[];
    float* s_x    = sm;
    float* s_proj = sm + 8192;
    float* s_u    = sm + 9472;
    int b = blockIdx.x, tid = threadIdx.x;
    for (int i = tid; i < 40*256; i += 256) s_u[i] = x_w[i];
    __syncthreads();
    for (int idx = tid; idx < DDim*256; idx += 256){
        int t = idx >> 8, j = idx & 255;
        float a = conv_b[j];
#pragma unroll
        for (int k = 0; k < 4; k++){
            int tt = t + k - 3;
            if (tt >= 0) a += g_xr[(b*DDim + tt)*256 + j] * conv_w[j*4 + k];
        }
        s_x[idx] = a * sigmoidf_(a);
    }
    __syncthreads();
    for (int idx = tid; idx < DDim*40; idx += 256){
        int t = idx / 40, q = idx % 40;
        float a = 0.f;
        const float* u = s_x + t*256;
        const float* w = s_u + q*256;
        for (int j = 0; j < 256; j++) a += u[j]*w[j];
        s_proj[idx] = a;
    }
    __syncthreads();
    for (int idx = tid; idx < DDim*256; idx += 256){
        int t = idx >> 8, j = idx & 255;
        float a = dt_b[j];
#pragma unroll
        for (int r = 0; r < 8; r++) a += s_proj[t*40 + r]*dt_w[j*8 + r];
        s_u[idx] = (a > 20.f) ? a : log1pf(expf(a));
    }
    __syncthreads();
    {
        int dch = tid;
        float A[16], h[16];
#pragma unroll
        for (int n = 0; n < 16; n++){ A[n] = -expf(A_log[dch*16 + n]); h[n] = 0.f; }
        float Dv = Dp[dch];
        for (int t = 0; t < DDim; t++){
            float dtv = s_u[t*256 + dch];
            float xv  = s_x[t*256 + dch];
            float y = 0.f;
#pragma unroll
            for (int n = 0; n < 16; n++){
                float dA = expf(dtv * A[n]);
                h[n] = dA*h[n] + dtv * s_proj[t*40 + 8 + n] * xv;
                y += h[n] * s_proj[t*40 + 24 + n];
            }
            y += xv * Dv;
            float zv = g_z[(b*DDim + t)*256 + dch];
            y *= zv * sigmoidf_(zv);
            g_y[(b*DDim + t)*256 + dch] = y;
        }
    }
}

__global__ __launch_bounds__(128)
void k_m4(const float* __restrict__ out_w, const float* __restrict__ W_t2){
    __shared__ float sy[256];
    __shared__ float som[HIDc];
    int bt = blockIdx.x, tid = threadIdx.x;
    int b = bt >> 5, t = bt & 31;
    sy[tid]       = g_y[bt*256 + tid];
    sy[tid + 128] = g_y[bt*256 + 128 + tid];
    __syncthreads();
    {
        const float* w = out_w + (size_t)tid*256;
        float a = 0.f;
#pragma unroll 4
        for (int j = 0; j < 256; j++) a += sy[j]*w[j];
        som[tid] = a;
    }
    __syncthreads();
    {
        const float* w = W_t2 + (size_t)tid*HIDc;
        float a = 0.f;
#pragma unroll 4
        for (int c = 0; c < HIDc; c++) a += som[c]*w[c];
        g_gate[(b*HIDc + tid)*DDim + t] = sigmoidf_(a);
    }
}

// ---------------- K4: fp16 mma conv, zero-predicate inner loop ---------------
// Stage = s in [0,72): cc=s&7, kh=(s>>3)%3, kd=s/24; all halos pre-padded.
// buf = [weights 12288B][input 4r x 8c2 x 72 u32 = 9216B]
#define INBOFF 12288
#define BUFB   21504
__global__ __launch_bounds__(512)
void k_conv_mma(){
    extern __shared__ __align__(128) char smem[];
    __shared__ __align__(8) unsigned long long mbars[2];
    unsigned usb = s2u(smem);
    unsigned umb = s2u(mbars);
    int tid = threadIdx.x, lane = tid & 31, wid = tid >> 5;
    int lq = lane >> 2, lr = lane & 3;
    int mw = wid >> 2, nw = wid & 3;
    int bid = blockIdx.x;
    int ht = bid % 14, d = (bid/14) & 31, b = bid / (14*32);
    int h0 = ht * 4;

    if (tid == 0){
        asm volatile("mbarrier.init.shared.b64 [%0], 1;" :: "r"(umb) : "memory");
        asm volatile("mbarrier.init.shared.b64 [%0], 1;" :: "r"(umb + 8) : "memory");
    }
    __syncthreads();

    auto issue = [&](int s){
        int buf = s & 1;
        int cc = s & 7, kh = (s >> 3) % 3, kd = s / 24;
        if (tid == 0)
            asm volatile("mbarrier.arrive.expect_tx.shared.b64 _, [%0], %1;"
                         :: "r"(umb + buf*8), "r"(21504u) : "memory");
        if (tid < 4){
            int r = tid;
            const unsigned* src = (const unsigned*)g_dwP +
                (((size_t)(b*34 + d + kd)*60 + (h0 + kh + r))*64 + cc*8)*72;
            bulkcp(usb + (unsigned)(buf*BUFB + INBOFF + r*2304), src, 2304u, umb + buf*8);
        } else if (tid == 4){
            bulkcp(usb + (unsigned)(buf*BUFB), g_wTh + (size_t)s*3072, 12288u, umb + buf*8);
        }
    };

    float acc[2][7][4];
#pragma unroll
    for (int t = 0; t < 2; t++)
#pragma unroll
        for (int nt = 0; nt < 7; nt++)
#pragma unroll
            for (int j = 0; j < 4; j++) acc[t][nt][j] = 0.f;

    issue(0);
    for (int s = 0; s < 72; s++){
        if (s < 71) issue(s + 1);
        bwait(umb + (s&1)*8, (unsigned)((s >> 1) & 1));
        const char* buf = smem + (s&1)*BUFB;
        const uint4* wp = (const uint4*)buf;
        const unsigned* ibl = (const unsigned*)(buf + INBOFF) + (nw*8 + lr)*72 + lq;
#pragma unroll
        for (int kw = 0; kw < 3; kw++){
            uint4 A0 = wp[(kw*8 + mw*2    )*32 + lane];
            uint4 A1 = wp[(kw*8 + mw*2 + 1)*32 + lane];
#pragma unroll
            for (int nt = 0; nt < 7; nt++){
                unsigned b0 = ibl[nt*8 + kw];
                unsigned b1 = ibl[nt*8 + kw + 288];
                mma16f(acc[0][nt], A0, b0, b1);
                mma16f(acc[1][nt], A1, b0, b1);
            }
        }
        __syncthreads();
    }

    int h = h0 + nw;
#pragma unroll
    for (int t = 0; t < 2; t++){
        int o = (mw*2 + t)*16 + lq;
        float* base0 = g_x1c + ((size_t)(b*HIDc + o))*PP + (size_t)d*HW + h*56;
#pragma unroll
        for (int nt = 0; nt < 7; nt++){
            int w = nt*8 + 2*lr;
            float2 v0, v1;
            v0.x = fmaxf(acc[t][nt][0], 0.f); v0.y = fmaxf(acc[t][nt][1], 0.f);
            v1.x = fmaxf(acc[t][nt][2], 0.f); v1.y = fmaxf(acc[t][nt][3], 0.f);
            *(float2*)(base0 + w) = v0;
            *(float2*)(base0 + (size_t)8*PP + w) = v1;
        }
    }
}

// ---------------- K5: gate + proj_out ----------------
__global__ __launch_bounds__(256)
void k_final(const float* __restrict__ W_out, float* __restrict__ out){
    __shared__ float sw[HIDc*64];
    int tid = threadIdx.x;
    for (int i = tid; i < HIDc*64; i += 256){
        int c = i >> 6, o = i & 63;
        sw[i] = W_out[o*HIDc + c];
    }
    __syncthreads();
    int b = blockIdx.y;
    int p = blockIdx.x*256 + tid;
    int d = p / HW;
    float acc[64];
#pragma unroll
    for (int o = 0; o < 64; o++) acc[o] = 0.f;
    const float* src  = g_x1c + (size_t)b*HIDc*PP + p;
    const float* gate = g_gate + b*HIDc*DDim + d;
    for (int c = 0; c < HIDc; c++){
        float v = src[(size_t)c*PP] * gate[c*DDim];
        const float4* wr = (const float4*)(sw + c*64);
#pragma unroll
        for (int q = 0; q < 16; q++){
            float4 w = wr[q];
            acc[4*q]   += v*w.x;
            acc[4*q+1] += v*w.y;
            acc[4*q+2] += v*w.z;
            acc[4*q+3] += v*w.w;
        }
    }
    float* dst = out + (size_t)b*64*PP + p;
#pragma unroll
    for (int o = 0; o < 64; o++) dst[(size_t)o*PP] = acc[o];
}

// ---------------- launch ----------------
extern "C" void kernel_launch(void* const* d_in, const int* in_sizes, int n_in,
                              void* d_out, int out_size){
    const float* inp      = (const float*)d_in[0];
    const float* W_in     = (const float*)d_in[1];
    const float* W_dw     = (const float*)d_in[2];
    const float* W_s      = (const float*)d_in[3];
    const float* W_t1     = (const float*)d_in[4];
    const float* W_t2     = (const float*)d_in[5];
    const float* m_in_w   = (const float*)d_in[6];
    const float* m_conv_w = (const float*)d_in[7];
    const float* m_conv_b = (const float*)d_in[8];
    const float* m_x_w    = (const float*)d_in[9];
    const float* m_dt_w   = (const float*)d_in[10];
    const float* m_dt_b   = (const float*)d_in[11];
    const float* m_A_log  = (const float*)d_in[12];
    const float* m_D      = (const float*)d_in[13];
    const float* m_out_w  = (const float*)d_in[14];
    const float* W_out    = (const float*)d_in[15];
    float* out = (float*)d_out;

    cudaFuncSetAttribute(k_projT, cudaFuncAttributeMaxDynamicSharedMemorySize, 51200);
    cudaFuncSetAttribute(k_m3,    cudaFuncAttributeMaxDynamicSharedMemorySize, 19712*4);
    cudaFuncSetAttribute(k_conv_mma, cudaFuncAttributeMaxDynamicSharedMemorySize, 2*BUFB);

    k_wtp     <<<32, 256>>>(W_in);
    k_projT   <<<dim3(784, Bb), 512, 51200>>>(inp);
    k_dw      <<<Bb*C2*DDim, 256>>>(W_dw);
    k_wt      <<<864, 256>>>(W_s);
    k_conv_mma<<<Bb*DDim*14, 512, 2*BUFB>>>();
    k_m1      <<<32, 256>>>(W_t1);
    k_m2      <<<128, 256>>>(m_in_w);
    k_m3      <<<Bb, 256, 19712*4>>>(m_conv_w, m_conv_b, m_x_w, m_dt_w,
                                     m_dt_b, m_A_log, m_D);
    k_m4      <<<64, 128>>>(m_out_w, W_t2);
    k_final   <<<dim3(PP/256, Bb), 256>>>(W_out, out);
}

// round 12
// speedup vs baseline: 3.3813x; 1.0540x over previous
#include <cuda_runtime.h>
#include <cuda_fp16.h>
#include <math.h>
#include <stdint.h>

#define Bb   2
#define CIN  64
#define HIDc 128
#define C2   256
#define DDim 32
#define HHe  56
#define WWi  56
#define HW   3136
#define PP   100352

__device__ float g_xz [Bb*(size_t)C2*PP];
__device__ float g_x1c[Bb*(size_t)HIDc*PP];
__device__ float g_pool[Bb*HIDc*DDim];
__device__ float g_gate[Bb*HIDc*DDim];
// fully halo-padded fp16 x1: [b][dp 34][hp 60][cc 8][c2 8][ws 72] u32-pairs; pads stay zero (CUDA zero-init)
__device__ __align__(16) unsigned short g_dwP[(size_t)Bb*34*60*64*72*2];
// fp16 A-frag packed conv weights: [s 72][kw 3][mt 8][lane 32][v 4] u32
__device__ __align__(16) unsigned g_wTh[72*3072];
// fp16 A-frag packed W_in: [ks 4][mt 16][lane 32][v 4] u32
__device__ __align__(16) unsigned g_pA[8192];
// mamba intermediates
__device__ float g_seq[Bb*DDim*HIDc];
__device__ float g_xr [Bb*DDim*256];
__device__ float g_z  [Bb*DDim*256];
__device__ float g_y  [Bb*DDim*256];

__device__ __forceinline__ float sigmoidf_(float x){ return 1.f/(1.f+expf(-x)); }
__device__ __forceinline__ unsigned s2u(const void* p){ unsigned a; asm("{ .reg .u64 t; cvta.to.shared.u64 t, %1; cvt.u32.u64 %0, t; }" : "=r"(a) : "l"(p)); return a; }
__device__ __forceinline__ void bwait(unsigned a, unsigned par){
    asm volatile("{\n\t.reg .pred P;\n\tLW%=:\n\tmbarrier.try_wait.parity.acquire.cta.shared::cta.b64 P, [%0], %1, 0x989680;\n\t@P bra.uni LD%=;\n\tbra.uni LW%=;\n\tLD%=:\n\t}" :: "r"(a), "r"(par) : "memory");
}
__device__ __forceinline__ void bulkcp(unsigned dst, const void* src, unsigned bytes, unsigned mbar){
    asm volatile("cp.async.bulk.shared::cluster.global.mbarrier::complete_tx::bytes [%0], [%1], %2, [%3];"
                 :: "r"(dst), "l"(src), "r"(bytes), "r"(mbar) : "memory");
}
__device__ __forceinline__ void mma16f(float* c, const uint4 a, unsigned b0, unsigned b1){
    asm volatile("mma.sync.aligned.m16n8k16.row.col.f32.f16.f16.f32 "
                 "{%0,%1,%2,%3}, {%4,%5,%6,%7}, {%8,%9}, {%0,%1,%2,%3};"
                 : "+f"(c[0]), "+f"(c[1]), "+f"(c[2]), "+f"(c[3])
                 : "r"(a.x), "r"(a.y), "r"(a.z), "r"(a.w), "r"(b0), "r"(b1));
}

// ---------------- K0: merged weight packers (conv Ws + proj W_in) ------------
__global__ __launch_bounds__(256)
void k_wpack(const float* __restrict__ Ws, const float* __restrict__ W_in){
    int bid = blockIdx.x;
    if (bid < 864){
        int i = bid*256 + threadIdx.x;           // exactly 72*3072
        int v = i & 3, lane = (i >> 2) & 31, mt = (i >> 7) & 7, kw = (i >> 10) % 3, s2 = i / 3072;
        int kd = s2 / 24, kh = (s2 >> 3) % 3, cc = s2 & 7;
        int lq = lane >> 2, lr = lane & 3;
        int o  = mt*16 + lq + 8*(v & 1);
        int c0 = cc*16 + 2*lr + 8*(v >> 1);
        int t27 = kd*9 + kh*3 + kw;
        __half2 h = __floats2half2_rn(Ws[((size_t)o*HIDc + c0)*27 + t27],
                                      Ws[((size_t)o*HIDc + c0 + 1)*27 + t27]);
        g_wTh[i] = *(unsigned*)&h;
    } else {
        int i = (bid - 864)*256 + threadIdx.x;   // exactly 8192
        int v = i & 3, lane = (i >> 2) & 31, mt = (i >> 7) & 15, ks = i >> 11;
        int o = mt*16 + (lane >> 2) + 8*(v & 1);
        int c = ks*16 + 2*(lane & 3) + 8*(v >> 1);
        __half2 h = __floats2half2_rn(W_in[o*CIN + c], W_in[o*CIN + c + 1]);
        g_pA[i] = *(unsigned*)&h;
    }
}

// ---------------- K1: proj_in via fp16 mma ----------------
__global__ __launch_bounds__(512)
void k_projT(const float* __restrict__ inp){
    extern __shared__ unsigned ps[];          // A 8192 u32 | B 4608 u32
    unsigned* sB = ps + 8192;
    uint4* sA4 = (uint4*)ps;
    int tid = threadIdx.x, lane = tid & 31, wid = tid >> 5;
    int lq = lane >> 2, lr = lane & 3;
    int mw = wid >> 2, nw = wid & 3;
    int b = blockIdx.y, p0 = blockIdx.x*128;
    const uint4* gA = (const uint4*)g_pA;
    for (int i = tid; i < 2048; i += 512) sA4[i] = gA[i];
    for (int i = tid; i < 4096; i += 512){
        int c2 = i >> 7, p = i & 127;
        float x0 = inp[((size_t)(b*CIN + 2*c2))*PP + p0 + p];
        float x1 = inp[((size_t)(b*CIN + 2*c2 + 1))*PP + p0 + p];
        __half2 h = __floats2half2_rn(x0, x1);
        sB[p*36 + c2] = *(unsigned*)&h;
    }
    __syncthreads();
    float acc[4][4][4];
#pragma unroll
    for (int t = 0; t < 4; t++)
#pragma unroll
        for (int nt = 0; nt < 4; nt++)
#pragma unroll
            for (int j = 0; j < 4; j++) acc[t][nt][j] = 0.f;
#pragma unroll
    for (int ks = 0; ks < 4; ks++){
        uint4 A[4];
#pragma unroll
        for (int t = 0; t < 4; t++) A[t] = sA4[(ks*16 + mw*4 + t)*32 + lane];
#pragma unroll
        for (int nt = 0; nt < 4; nt++){
            int pr = nw*32 + nt*8 + lq;
            unsigned b0 = sB[pr*36 + ks*8 + lr];
            unsigned b1 = sB[pr*36 + ks*8 + lr + 4];
#pragma unroll
            for (int t = 0; t < 4; t++) mma16f(acc[t][nt], A[t], b0, b1);
        }
    }
#pragma unroll
    for (int t = 0; t < 4; t++){
        int o = mw*64 + t*16 + lq;
        float* d0 = g_xz + ((size_t)(b*C2 + o))*PP + p0 + nw*32 + 2*lr;
#pragma unroll
        for (int nt = 0; nt < 4; nt++){
            float2 v0, v1;
            v0.x = acc[t][nt][0]; v0.y = acc[t][nt][1];
            v1.x = acc[t][nt][2]; v1.y = acc[t][nt][3];
            *(float2*)(d0 + nt*8) = v0;
            *(float2*)(d0 + (size_t)8*PP + nt*8) = v1;
        }
    }
}

// ---------------- K2: depthwise 3x3x3, rolling depth window ------------------
// Block = (b,c). 3-plane rolling smem window (each g_xz plane read ONCE).
// Thread computes a 4-wide w-quad via float4/float2 row loads (stride 60 -> aligned).
__global__ __launch_bounds__(256)
void k_dw(const float* __restrict__ W_dw){
    __shared__ float sp[3][60*58];
    __shared__ float red[8];
    int bid = blockIdx.x;
    int c = bid & 255, b = bid >> 8;
    int tid = threadIdx.x, lane = tid & 31, wid = tid >> 5;
    const float* src = g_xz + ((size_t)(b*C2 + c))*PP;
    float wv[27];
#pragma unroll
    for (int t = 0; t < 27; t++) wv[t] = W_dw[c*27 + t];

    auto load_plane = [&](int slot, int gd){
        if ((unsigned)gd < 32u){
            const float* p = src + gd*HW;
            for (int idx = tid; idx < 3480; idx += 256){
                int hh = idx / 60, ww = idx % 60;
                int gh = hh - 1, gw = ww - 1;
                float v = 0.f;
                if ((unsigned)gh < 56u && (unsigned)gw < 56u) v = p[gh*56 + gw];
                sp[slot][idx] = v;
            }
        } else {
            for (int idx = tid; idx < 3480; idx += 256) sp[slot][idx] = 0.f;
        }
    };
    // slot(dd) = (dd+1)%3 ; prologue: planes -1,0,1
    load_plane(0, -1);
    load_plane(1, 0);
    load_plane(2, 1);

    int cidx = (c >> 4)*8 + ((c >> 1) & 7);
    bool isX1 = (c < HIDc);
    for (int d = 0; d < 32; d++){
        __syncthreads();
        float psum = 0.f;
        for (int idx = tid; idx < 784; idx += 256){
            int h = idx / 14, w0 = (idx % 14)*4;
            float a0 = 0.f, a1 = 0.f, a2 = 0.f, a3 = 0.f;
#pragma unroll
            for (int kd = 0; kd < 3; kd++){
                const float* pl = sp[(d + kd) % 3];
#pragma unroll
                for (int kh = 0; kh < 3; kh++){
                    const float* row = pl + (h + kh)*60 + w0;
                    float4 r03 = *(const float4*)row;
                    float2 r45 = *(const float2*)(row + 4);
                    float wA = wv[kd*9 + kh*3], wB = wv[kd*9 + kh*3 + 1], wC = wv[kd*9 + kh*3 + 2];
                    a0 += r03.x*wA + r03.y*wB + r03.z*wC;
                    a1 += r03.y*wA + r03.z*wB + r03.w*wC;
                    a2 += r03.z*wA + r03.w*wB + r45.x*wC;
                    a3 += r03.w*wA + r45.x*wB + r45.y*wC;
                }
            }
            if (isX1){
                size_t base = ((((size_t)((b*34 + d + 1)*60) + h + 1)*64 + cidx)*72 + w0 + 1)*2 + (c & 1);
                g_dwP[base]     = __half_as_ushort(__float2half_rn(a0));
                g_dwP[base + 2] = __half_as_ushort(__float2half_rn(a1));
                g_dwP[base + 4] = __half_as_ushort(__float2half_rn(a2));
                g_dwP[base + 6] = __half_as_ushort(__float2half_rn(a3));
            }
            psum += a0 + a1 + a2 + a3;
        }
        if (!isX1){
#pragma unroll
            for (int off = 16; off > 0; off >>= 1) psum += __shfl_xor_sync(0xffffffffu, psum, off);
            if (lane == 0) red[wid] = psum;
            __syncthreads();
            if (tid == 0){
                float s = 0.f;
#pragma unroll
                for (int i = 0; i < 8; i++) s += red[i];
                g_pool[(b*HIDc + (c - HIDc))*DDim + d] = s * (1.f/HW);
            }
        }
        __syncthreads();
        load_plane(d % 3, d + 2);
    }
}

// ---------------- mamba chain ----------------
__global__ __launch_bounds__(256)
void k_m1(const float* __restrict__ W_t1){
    int idx = blockIdx.x*256 + threadIdx.x;
    int i = idx & 127, t = (idx >> 7) & 31, b = idx >> 12;
    const float* w  = W_t1 + i*HIDc;
    const float* pl = g_pool + b*HIDc*DDim + t;
    float a = 0.f;
    for (int c = 0; c < HIDc; c++) a += w[c] * pl[c*DDim];
    g_seq[idx] = a;
}

__global__ __launch_bounds__(256)
void k_m2(const float* __restrict__ in_w){
    __shared__ float s[HIDc];
    int blk = blockIdx.x, tid = threadIdx.x;
    int half = blk & 1, t = (blk >> 1) & 31, b = blk >> 6;
    if (tid < HIDc) s[tid] = g_seq[(b*DDim + t)*HIDc + tid];
    __syncthreads();
    int j = half*256 + tid;
    const float* w = in_w + (size_t)j*HIDc;
    float a = 0.f;
#pragma unroll 4
    for (int i = 0; i < HIDc; i++) a += s[i]*w[i];
    if (half == 0) g_xr[(b*DDim + t)*256 + tid] = a;
    else           g_z [(b*DDim + t)*256 + tid] = a;
}

__global__ __launch_bounds__(256)
void k_m3(const float* __restrict__ conv_w, const float* __restrict__ conv_b,
          const float* __restrict__ x_w, const float* __restrict__ dt_w,
          const float* __restrict__ dt_b, const float* __restrict__ A_log,
          const float* __restrict__ Dp){
    extern __shared__ float sm[];
    float* s_x    = sm;
    float* s_proj = sm + 8192;
    float* s_u    = sm + 9472;
    int b = blockIdx.x, tid = threadIdx.x;
    for (int i = tid; i < 40*256; i += 256) s_u[i] = x_w[i];
    __syncthreads();
    for (int idx = tid; idx < DDim*256; idx += 256){
        int t = idx >> 8, j = idx & 255;
        float a = conv_b[j];
#pragma unroll
        for (int k = 0; k < 4; k++){
            int tt = t + k - 3;
            if (tt >= 0) a += g_xr[(b*DDim + tt)*256 + j] * conv_w[j*4 + k];
        }
        s_x[idx] = a * sigmoidf_(a);
    }
    __syncthreads();
    for (int idx = tid; idx < DDim*40; idx += 256){
        int t = idx / 40, q = idx % 40;
        float a = 0.f;
        const float* u = s_x + t*256;
        const float* w = s_u + q*256;
        for (int j = 0; j < 256; j++) a += u[j]*w[j];
        s_proj[idx] = a;
    }
    __syncthreads();
    for (int idx = tid; idx < DDim*256; idx += 256){
        int t = idx >> 8, j = idx & 255;
        float a = dt_b[j];
#pragma unroll
        for (int r = 0; r < 8; r++) a += s_proj[t*40 + r]*dt_w[j*8 + r];
        s_u[idx] = (a > 20.f) ? a : log1pf(expf(a));
    }
    __syncthreads();
    {
        int dch = tid;
        float A[16], h[16];
#pragma unroll
        for (int n = 0; n < 16; n++){ A[n] = -expf(A_log[dch*16 + n]); h[n] = 0.f; }
        float Dv = Dp[dch];
        for (int t = 0; t < DDim; t++){
            float dtv = s_u[t*256 + dch];
            float xv  = s_x[t*256 + dch];
            float y = 0.f;
#pragma unroll
            for (int n = 0; n < 16; n++){
                float dA = expf(dtv * A[n]);
                h[n] = dA*h[n] + dtv * s_proj[t*40 + 8 + n] * xv;
                y += h[n] * s_proj[t*40 + 24 + n];
            }
            y += xv * Dv;
            float zv = g_z[(b*DDim + t)*256 + dch];
            y *= zv * sigmoidf_(zv);
            g_y[(b*DDim + t)*256 + dch] = y;
        }
    }
}

__global__ __launch_bounds__(128)
void k_m4(const float* __restrict__ out_w, const float* __restrict__ W_t2){
    __shared__ float sy[256];
    __shared__ float som[HIDc];
    int bt = blockIdx.x, tid = threadIdx.x;
    int b = bt >> 5, t = bt & 31;
    sy[tid]       = g_y[bt*256 + tid];
    sy[tid + 128] = g_y[bt*256 + 128 + tid];
    __syncthreads();
    {
        const float* w = out_w + (size_t)tid*256;
        float a = 0.f;
#pragma unroll 4
        for (int j = 0; j < 256; j++) a += sy[j]*w[j];
        som[tid] = a;
    }
    __syncthreads();
    {
        const float* w = W_t2 + (size_t)tid*HIDc;
        float a = 0.f;
#pragma unroll 4
        for (int c = 0; c < HIDc; c++) a += som[c]*w[c];
        g_gate[(b*HIDc + tid)*DDim + t] = sigmoidf_(a);
    }
}

// ---------------- K4: fp16 mma conv, zero-predicate inner loop ---------------
#define INBOFF 12288
#define BUFB   21504
__global__ __launch_bounds__(512)
void k_conv_mma(){
    extern __shared__ __align__(128) char smem[];
    __shared__ __align__(8) unsigned long long mbars[2];
    unsigned usb = s2u(smem);
    unsigned umb = s2u(mbars);
    int tid = threadIdx.x, lane = tid & 31, wid = tid >> 5;
    int lq = lane >> 2, lr = lane & 3;
    int mw = wid >> 2, nw = wid & 3;
    int bid = blockIdx.x;
    int ht = bid % 14, d = (bid/14) & 31, b = bid / (14*32);
    int h0 = ht * 4;

    if (tid == 0){
        asm volatile("mbarrier.init.shared.b64 [%0], 1;" :: "r"(umb) : "memory");
        asm volatile("mbarrier.init.shared.b64 [%0], 1;" :: "r"(umb + 8) : "memory");
    }
    __syncthreads();

    auto issue = [&](int s){
        int buf = s & 1;
        int cc = s & 7, kh = (s >> 3) % 3, kd = s / 24;
        if (tid == 0)
            asm volatile("mbarrier.arrive.expect_tx.shared.b64 _, [%0], %1;"
                         :: "r"(umb + buf*8), "r"(21504u) : "memory");
        if (tid < 4){
            int r = tid;
            const unsigned* src = (const unsigned*)g_dwP +
                (((size_t)(b*34 + d + kd)*60 + (h0 + kh + r))*64 + cc*8)*72;
            bulkcp(usb + (unsigned)(buf*BUFB + INBOFF + r*2304), src, 2304u, umb + buf*8);
        } else if (tid == 4){
            bulkcp(usb + (unsigned)(buf*BUFB), g_wTh + (size_t)s*3072, 12288u, umb + buf*8);
        }
    };

    float acc[2][7][4];
#pragma unroll
    for (int t = 0; t < 2; t++)
#pragma unroll
        for (int nt = 0; nt < 7; nt++)
#pragma unroll
            for (int j = 0; j < 4; j++) acc[t][nt][j] = 0.f;

    issue(0);
    for (int s = 0; s < 72; s++){
        if (s < 71) issue(s + 1);
        bwait(umb + (s&1)*8, (unsigned)((s >> 1) & 1));
        const char* buf = smem + (s&1)*BUFB;
        const uint4* wp = (const uint4*)buf;
        const unsigned* ibl = (const unsigned*)(buf + INBOFF) + (nw*8 + lr)*72 + lq;
#pragma unroll
        for (int kw = 0; kw < 3; kw++){
            uint4 A0 = wp[(kw*8 + mw*2    )*32 + lane];
            uint4 A1 = wp[(kw*8 + mw*2 + 1)*32 + lane];
#pragma unroll
            for (int nt = 0; nt < 7; nt++){
                unsigned b0 = ibl[nt*8 + kw];
                unsigned b1 = ibl[nt*8 + kw + 288];
                mma16f(acc[0][nt], A0, b0, b1);
                mma16f(acc[1][nt], A1, b0, b1);
            }
        }
        __syncthreads();
    }

    int h = h0 + nw;
#pragma unroll
    for (int t = 0; t < 2; t++){
        int o = (mw*2 + t)*16 + lq;
        float* base0 = g_x1c + ((size_t)(b*HIDc + o))*PP + (size_t)d*HW + h*56;
#pragma unroll
        for (int nt = 0; nt < 7; nt++){
            int w = nt*8 + 2*lr;
            float2 v0, v1;
            v0.x = fmaxf(acc[t][nt][0], 0.f); v0.y = fmaxf(acc[t][nt][1], 0.f);
            v1.x = fmaxf(acc[t][nt][2], 0.f); v1.y = fmaxf(acc[t][nt][3], 0.f);
            *(float2*)(base0 + w) = v0;
            *(float2*)(base0 + (size_t)8*PP + w) = v1;
        }
    }
}

// ---------------- K5: gate + proj_out ----------------
__global__ __launch_bounds__(256)
void k_final(const float* __restrict__ W_out, float* __restrict__ out){
    __shared__ float sw[HIDc*64];
    int tid = threadIdx.x;
    for (int i = tid; i < HIDc*64; i += 256){
        int c = i >> 6, o = i & 63;
        sw[i] = W_out[o*HIDc + c];
    }
    __syncthreads();
    int b = blockIdx.y;
    int p = blockIdx.x*256 + tid;
    int d = p / HW;
    float acc[64];
#pragma unroll
    for (int o = 0; o < 64; o++) acc[o] = 0.f;
    const float* src  = g_x1c + (size_t)b*HIDc*PP + p;
    const float* gate = g_gate + b*HIDc*DDim + d;
    for (int c = 0; c < HIDc; c++){
        float v = src[(size_t)c*PP] * gate[c*DDim];
        const float4* wr = (const float4*)(sw + c*64);
#pragma unroll
        for (int q = 0; q < 16; q++){
            float4 w = wr[q];
            acc[4*q]   += v*w.x;
            acc[4*q+1] += v*w.y;
            acc[4*q+2] += v*w.z;
            acc[4*q+3] += v*w.w;
        }
    }
    float* dst = out + (size_t)b*64*PP + p;
#pragma unroll
    for (int o = 0; o < 64; o++) dst[(size_t)o*PP] = acc[o];
}

// ---------------- launch ----------------
extern "C" void kernel_launch(void* const* d_in, const int* in_sizes, int n_in,
                              void* d_out, int out_size){
    const float* inp      = (const float*)d_in[0];
    const float* W_in     = (const float*)d_in[1];
    const float* W_dw     = (const float*)d_in[2];
    const float* W_s      = (const float*)d_in[3];
    const float* W_t1     = (const float*)d_in[4];
    const float* W_t2     = (const float*)d_in[5];
    const float* m_in_w   = (const float*)d_in[6];
    const float* m_conv_w = (const float*)d_in[7];
    const float* m_conv_b = (const float*)d_in[8];
    const float* m_x_w    = (const float*)d_in[9];
    const float* m_dt_w   = (const float*)d_in[10];
    const float* m_dt_b   = (const float*)d_in[11];
    const float* m_A_log  = (const float*)d_in[12];
    const float* m_D      = (const float*)d_in[13];
    const float* m_out_w  = (const float*)d_in[14];
    const float* W_out    = (const float*)d_in[15];
    float* out = (float*)d_out;

    cudaFuncSetAttribute(k_projT, cudaFuncAttributeMaxDynamicSharedMemorySize, 51200);
    cudaFuncSetAttribute(k_m3,    cudaFuncAttributeMaxDynamicSharedMemorySize, 19712*4);
    cudaFuncSetAttribute(k_conv_mma, cudaFuncAttributeMaxDynamicSharedMemorySize, 2*BUFB);

    k_wpack   <<<896, 256>>>(W_s, W_in);                          // idx 0
    k_projT   <<<dim3(784, Bb), 512, 51200>>>(inp);               // idx 1
    k_dw      <<<Bb*C2, 256>>>(W_dw);                             // idx 2
    k_conv_mma<<<Bb*DDim*14, 512, 2*BUFB>>>();                    // idx 3 (profiled slot)
    k_m1      <<<32, 256>>>(W_t1);
    k_m2      <<<128, 256>>>(m_in_w);
    k_m3      <<<Bb, 256, 19712*4>>>(m_conv_w, m_conv_b, m_x_w, m_dt_w,
                                     m_dt_b, m_A_log, m_D);
    k_m4      <<<64, 128>>>(m_out_w, W_t2);
    k_final   <<<dim3(PP/256, Bb), 256>>>(W_out, out);
}

// round 13
// speedup vs baseline: 3.8797x; 1.1474x over previous
#include <cuda_runtime.h>
#include <cuda_fp16.h>
#include <math.h>
#include <stdint.h>

#define Bb   2
#define CIN  64
#define HIDc 128
#define C2   256
#define DDim 32
#define HHe  56
#define WWi  56
#define HW   3136
#define PP   100352

__device__ float g_xz [Bb*(size_t)C2*PP];
__device__ float g_x1c[Bb*(size_t)HIDc*PP];
__device__ float g_pool[Bb*HIDc*DDim];
__device__ float g_gate[Bb*HIDc*DDim];
// fully halo-padded fp16 x1: [b][dp 34][hp 60][cc 8][c2 8][ws 72] u32-pairs; pads stay zero
__device__ __align__(16) unsigned short g_dwP[(size_t)Bb*34*60*64*72*2];
// fp16 A-frag packed conv weights: [s 72][kw 3][mt 8][lane 32][v 4] u32
__device__ __align__(16) unsigned g_wTh[72*3072];
// fp16 A-frag packed W_in: [ks 4][mt 16][lane 32][v 4] u32
__device__ __align__(16) unsigned g_pA[8192];
// fp16 A-frag packed W_out: [mt 4][ks 8][lane 32][v 4] u32
__device__ __align__(16) unsigned g_fA[4096];
// mamba intermediates
__device__ float g_seq[Bb*DDim*HIDc];
__device__ float g_xr [Bb*DDim*256];
__device__ float g_z  [Bb*DDim*256];
__device__ float g_y  [Bb*DDim*256];

__device__ __forceinline__ float sigmoidf_(float x){ return 1.f/(1.f+expf(-x)); }
__device__ __forceinline__ unsigned s2u(const void* p){ unsigned a; asm("{ .reg .u64 t; cvta.to.shared.u64 t, %1; cvt.u32.u64 %0, t; }" : "=r"(a) : "l"(p)); return a; }
__device__ __forceinline__ void bwait(unsigned a, unsigned par){
    asm volatile("{\n\t.reg .pred P;\n\tLW%=:\n\tmbarrier.try_wait.parity.acquire.cta.shared::cta.b64 P, [%0], %1, 0x989680;\n\t@P bra.uni LD%=;\n\tbra.uni LW%=;\n\tLD%=:\n\t}" :: "r"(a), "r"(par) : "memory");
}
__device__ __forceinline__ void bulkcp(unsigned dst, const void* src, unsigned bytes, unsigned mbar){
    asm volatile("cp.async.bulk.shared::cluster.global.mbarrier::complete_tx::bytes [%0], [%1], %2, [%3];"
                 :: "r"(dst), "l"(src), "r"(bytes), "r"(mbar) : "memory");
}
__device__ __forceinline__ void mma16f(float* c, const uint4 a, unsigned b0, unsigned b1){
    asm volatile("mma.sync.aligned.m16n8k16.row.col.f32.f16.f16.f32 "
                 "{%0,%1,%2,%3}, {%4,%5,%6,%7}, {%8,%9}, {%0,%1,%2,%3};"
                 : "+f"(c[0]), "+f"(c[1]), "+f"(c[2]), "+f"(c[3])
                 : "r"(a.x), "r"(a.y), "r"(a.z), "r"(a.w), "r"(b0), "r"(b1));
}

// ---------------- K0: merged weight packers (conv Ws + W_in + W_out) ---------
__global__ __launch_bounds__(256)
void k_wpack(const float* __restrict__ Ws, const float* __restrict__ W_in,
             const float* __restrict__ W_out){
    int bid = blockIdx.x;
    if (bid < 864){
        int i = bid*256 + threadIdx.x;
        int v = i & 3, lane = (i >> 2) & 31, mt = (i >> 7) & 7, kw = (i >> 10) % 3, s2 = i / 3072;
        int kd = s2 / 24, kh = (s2 >> 3) % 3, cc = s2 & 7;
        int lq = lane >> 2, lr = lane & 3;
        int o  = mt*16 + lq + 8*(v & 1);
        int c0 = cc*16 + 2*lr + 8*(v >> 1);
        int t27 = kd*9 + kh*3 + kw;
        __half2 h = __floats2half2_rn(Ws[((size_t)o*HIDc + c0)*27 + t27],
                                      Ws[((size_t)o*HIDc + c0 + 1)*27 + t27]);
        g_wTh[i] = *(unsigned*)&h;
    } else if (bid < 896){
        int i = (bid - 864)*256 + threadIdx.x;
        int v = i & 3, lane = (i >> 2) & 31, mt = (i >> 7) & 15, ks = i >> 11;
        int o = mt*16 + (lane >> 2) + 8*(v & 1);
        int c = ks*16 + 2*(lane & 3) + 8*(v >> 1);
        __half2 h = __floats2half2_rn(W_in[o*CIN + c], W_in[o*CIN + c + 1]);
        g_pA[i] = *(unsigned*)&h;
    } else {
        int i = (bid - 896)*256 + threadIdx.x;   // 4096 = 16 blocks
        int v = i & 3, lane = (i >> 2) & 31, ks = (i >> 7) & 7, mt = i >> 10;
        int o = mt*16 + (lane >> 2) + 8*(v & 1);
        int c = ks*16 + 2*(lane & 3) + 8*(v >> 1);
        __half2 h = __floats2half2_rn(W_out[o*HIDc + c], W_out[o*HIDc + c + 1]);
        g_fA[i] = *(unsigned*)&h;
    }
}

// ---------------- K1: proj_in via fp16 mma ----------------
__global__ __launch_bounds__(512)
void k_projT(const float* __restrict__ inp){
    extern __shared__ unsigned ps[];          // A 8192 u32 | B 4608 u32
    unsigned* sB = ps + 8192;
    uint4* sA4 = (uint4*)ps;
    int tid = threadIdx.x, lane = tid & 31, wid = tid >> 5;
    int lq = lane >> 2, lr = lane & 3;
    int mw = wid >> 2, nw = wid & 3;
    int b = blockIdx.y, p0 = blockIdx.x*128;
    const uint4* gA = (const uint4*)g_pA;
    for (int i = tid; i < 2048; i += 512) sA4[i] = gA[i];
    for (int i = tid; i < 4096; i += 512){
        int c2 = i >> 7, p = i & 127;
        float x0 = inp[((size_t)(b*CIN + 2*c2))*PP + p0 + p];
        float x1 = inp[((size_t)(b*CIN + 2*c2 + 1))*PP + p0 + p];
        __half2 h = __floats2half2_rn(x0, x1);
        sB[p*36 + c2] = *(unsigned*)&h;
    }
    __syncthreads();
    float acc[4][4][4];
#pragma unroll
    for (int t = 0; t < 4; t++)
#pragma unroll
        for (int nt = 0; nt < 4; nt++)
#pragma unroll
            for (int j = 0; j < 4; j++) acc[t][nt][j] = 0.f;
#pragma unroll
    for (int ks = 0; ks < 4; ks++){
        uint4 A[4];
#pragma unroll
        for (int t = 0; t < 4; t++) A[t] = sA4[(ks*16 + mw*4 + t)*32 + lane];
#pragma unroll
        for (int nt = 0; nt < 4; nt++){
            int pr = nw*32 + nt*8 + lq;
            unsigned b0 = sB[pr*36 + ks*8 + lr];
            unsigned b1 = sB[pr*36 + ks*8 + lr + 4];
#pragma unroll
            for (int t = 0; t < 4; t++) mma16f(acc[t][nt], A[t], b0, b1);
        }
    }
#pragma unroll
    for (int t = 0; t < 4; t++){
        int o = mw*64 + t*16 + lq;
        float* d0 = g_xz + ((size_t)(b*C2 + o))*PP + p0 + nw*32 + 2*lr;
#pragma unroll
        for (int nt = 0; nt < 4; nt++){
            float2 v0, v1;
            v0.x = acc[t][nt][0]; v0.y = acc[t][nt][1];
            v1.x = acc[t][nt][2]; v1.y = acc[t][nt][3];
            *(float2*)(d0 + nt*8) = v0;
            *(float2*)(d0 + (size_t)8*PP + nt*8) = v1;
        }
    }
}

// ---------------- K2: depthwise 3x3x3, rolling depth window ------------------
__global__ __launch_bounds__(256)
void k_dw(const float* __restrict__ W_dw){
    __shared__ float sp[3][60*58];
    __shared__ float red[8];
    int bid = blockIdx.x;
    int c = bid & 255, b = bid >> 8;
    int tid = threadIdx.x, lane = tid & 31, wid = tid >> 5;
    const float* src = g_xz + ((size_t)(b*C2 + c))*PP;
    float wv[27];
#pragma unroll
    for (int t = 0; t < 27; t++) wv[t] = W_dw[c*27 + t];

    auto load_plane = [&](int slot, int gd){
        if ((unsigned)gd < 32u){
            const float* p = src + gd*HW;
            for (int idx = tid; idx < 3480; idx += 256){
                int hh = idx / 60, ww = idx % 60;
                int gh = hh - 1, gw = ww - 1;
                float v = 0.f;
                if ((unsigned)gh < 56u && (unsigned)gw < 56u) v = p[gh*56 + gw];
                sp[slot][idx] = v;
            }
        } else {
            for (int idx = tid; idx < 3480; idx += 256) sp[slot][idx] = 0.f;
        }
    };
    load_plane(0, -1);
    load_plane(1, 0);
    load_plane(2, 1);

    int cidx = (c >> 4)*8 + ((c >> 1) & 7);
    bool isX1 = (c < HIDc);
    for (int d = 0; d < 32; d++){
        __syncthreads();
        float psum = 0.f;
        for (int idx = tid; idx < 784; idx += 256){
            int h = idx / 14, w0 = (idx % 14)*4;
            float a0 = 0.f, a1 = 0.f, a2 = 0.f, a3 = 0.f;
#pragma unroll
            for (int kd = 0; kd < 3; kd++){
                const float* pl = sp[(d + kd) % 3];
#pragma unroll
                for (int kh = 0; kh < 3; kh++){
                    const float* row = pl + (h + kh)*60 + w0;
                    float4 r03 = *(const float4*)row;
                    float2 r45 = *(const float2*)(row + 4);
                    float wA = wv[kd*9 + kh*3], wB = wv[kd*9 + kh*3 + 1], wC = wv[kd*9 + kh*3 + 2];
                    a0 += r03.x*wA + r03.y*wB + r03.z*wC;
                    a1 += r03.y*wA + r03.z*wB + r03.w*wC;
                    a2 += r03.z*wA + r03.w*wB + r45.x*wC;
                    a3 += r03.w*wA + r45.x*wB + r45.y*wC;
                }
            }
            if (isX1){
                size_t base = ((((size_t)((b*34 + d + 1)*60) + h + 1)*64 + cidx)*72 + w0 + 1)*2 + (c & 1);
                g_dwP[base]     = __half_as_ushort(__float2half_rn(a0));
                g_dwP[base + 2] = __half_as_ushort(__float2half_rn(a1));
                g_dwP[base + 4] = __half_as_ushort(__float2half_rn(a2));
                g_dwP[base + 6] = __half_as_ushort(__float2half_rn(a3));
            }
            psum += a0 + a1 + a2 + a3;
        }
        if (!isX1){
#pragma unroll
            for (int off = 16; off > 0; off >>= 1) psum += __shfl_xor_sync(0xffffffffu, psum, off);
            if (lane == 0) red[wid] = psum;
            __syncthreads();
            if (tid == 0){
                float s = 0.f;
#pragma unroll
                for (int i = 0; i < 8; i++) s += red[i];
                g_pool[(b*HIDc + (c - HIDc))*DDim + d] = s * (1.f/HW);
            }
        }
        __syncthreads();
        load_plane(d % 3, d + 2);
    }
}

// ---------------- mamba chain ----------------
__global__ __launch_bounds__(256)
void k_m1(const float* __restrict__ W_t1){
    int idx = blockIdx.x*256 + threadIdx.x;
    int i = idx & 127, t = (idx >> 7) & 31, b = idx >> 12;
    const float* w  = W_t1 + i*HIDc;
    const float* pl = g_pool + b*HIDc*DDim + t;
    float a = 0.f;
    for (int c = 0; c < HIDc; c++) a += w[c] * pl[c*DDim];
    g_seq[idx] = a;
}

__global__ __launch_bounds__(256)
void k_m2(const float* __restrict__ in_w){
    __shared__ float s[HIDc];
    int blk = blockIdx.x, tid = threadIdx.x;
    int half = blk & 1, t = (blk >> 1) & 31, b = blk >> 6;
    if (tid < HIDc) s[tid] = g_seq[(b*DDim + t)*HIDc + tid];
    __syncthreads();
    int j = half*256 + tid;
    const float* w = in_w + (size_t)j*HIDc;
    float a = 0.f;
#pragma unroll 4
    for (int i = 0; i < HIDc; i++) a += s[i]*w[i];
    if (half == 0) g_xr[(b*DDim + t)*256 + tid] = a;
    else           g_z [(b*DDim + t)*256 + tid] = a;
}

__global__ __launch_bounds__(256)
void k_m3(const float* __restrict__ conv_w, const float* __restrict__ conv_b,
          const float* __restrict__ x_w, const float* __restrict__ dt_w,
          const float* __restrict__ dt_b, const float* __restrict__ A_log,
          const float* __restrict__ Dp){
    extern __shared__ float sm[];
    float* s_x    = sm;
    float* s_proj = sm + 8192;
    float* s_u    = sm + 9472;
    int b = blockIdx.x, tid = threadIdx.x;
    for (int i = tid; i < 40*256; i += 256) s_u[i] = x_w[i];
    __syncthreads();
    for (int idx = tid; idx < DDim*256; idx += 256){
        int t = idx >> 8, j = idx & 255;
        float a = conv_b[j];
#pragma unroll
        for (int k = 0; k < 4; k++){
            int tt = t + k - 3;
            if (tt >= 0) a += g_xr[(b*DDim + tt)*256 + j] * conv_w[j*4 + k];
        }
        s_x[idx] = a * sigmoidf_(a);
    }
    __syncthreads();
    for (int idx = tid; idx < DDim*40; idx += 256){
        int t = idx / 40, q = idx % 40;
        float a = 0.f;
        const float* u = s_x + t*256;
        const float* w = s_u + q*256;
        for (int j = 0; j < 256; j++) a += u[j]*w[j];
        s_proj[idx] = a;
    }
    __syncthreads();
    for (int idx = tid; idx < DDim*256; idx += 256){
        int t = idx >> 8, j = idx & 255;
        float a = dt_b[j];
#pragma unroll
        for (int r = 0; r < 8; r++) a += s_proj[t*40 + r]*dt_w[j*8 + r];
        s_u[idx] = (a > 20.f) ? a : log1pf(expf(a));
    }
    __syncthreads();
    {
        int dch = tid;
        float A[16], h[16];
#pragma unroll
        for (int n = 0; n < 16; n++){ A[n] = -expf(A_log[dch*16 + n]); h[n] = 0.f; }
        float Dv = Dp[dch];
        for (int t = 0; t < DDim; t++){
            float dtv = s_u[t*256 + dch];
            float xv  = s_x[t*256 + dch];
            float y = 0.f;
#pragma unroll
            for (int n = 0; n < 16; n++){
                float dA = expf(dtv * A[n]);
                h[n] = dA*h[n] + dtv * s_proj[t*40 + 8 + n] * xv;
                y += h[n] * s_proj[t*40 + 24 + n];
            }
            y += xv * Dv;
            float zv = g_z[(b*DDim + t)*256 + dch];
            y *= zv * sigmoidf_(zv);
            g_y[(b*DDim + t)*256 + dch] = y;
        }
    }
}

__global__ __launch_bounds__(128)
void k_m4(const float* __restrict__ out_w, const float* __restrict__ W_t2){
    __shared__ float sy[256];
    __shared__ float som[HIDc];
    int bt = blockIdx.x, tid = threadIdx.x;
    int b = bt >> 5, t = bt & 31;
    sy[tid]       = g_y[bt*256 + tid];
    sy[tid + 128] = g_y[bt*256 + 128 + tid];
    __syncthreads();
    {
        const float* w = out_w + (size_t)tid*256;
        float a = 0.f;
#pragma unroll 4
        for (int j = 0; j < 256; j++) a += sy[j]*w[j];
        som[tid] = a;
    }
    __syncthreads();
    {
        const float* w = W_t2 + (size_t)tid*HIDc;
        float a = 0.f;
#pragma unroll 4
        for (int c = 0; c < HIDc; c++) a += som[c]*w[c];
        g_gate[(b*HIDc + tid)*DDim + t] = sigmoidf_(a);
    }
}

// ---------------- K4: fp16 mma conv, 4-deep ring ---------------
#define INBOFF 12288
#define BUFB   21504
__global__ __launch_bounds__(512)
void k_conv_mma(){
    extern __shared__ __align__(128) char smem[];
    __shared__ __align__(8) unsigned long long mbars[4];
    unsigned usb = s2u(smem);
    unsigned umb = s2u(mbars);
    int tid = threadIdx.x, lane = tid & 31, wid = tid >> 5;
    int lq = lane >> 2, lr = lane & 3;
    int mw = wid >> 2, nw = wid & 3;
    int bid = blockIdx.x;
    int ht = bid % 14, d = (bid/14) & 31, b = bid / (14*32);
    int h0 = ht * 4;

    if (tid == 0){
#pragma unroll
        for (int i = 0; i < 4; i++)
            asm volatile("mbarrier.init.shared.b64 [%0], 1;" :: "r"(umb + i*8) : "memory");
    }
    __syncthreads();

    auto issue = [&](int s){
        int buf = s & 3;
        int cc = s & 7, kh = (s >> 3) % 3, kd = s / 24;
        if (tid == 0)
            asm volatile("mbarrier.arrive.expect_tx.shared.b64 _, [%0], %1;"
                         :: "r"(umb + buf*8), "r"(21504u) : "memory");
        if (tid < 4){
            int r = tid;
            const unsigned* src = (const unsigned*)g_dwP +
                (((size_t)(b*34 + d + kd)*60 + (h0 + kh + r))*64 + cc*8)*72;
            bulkcp(usb + (unsigned)(buf*BUFB + INBOFF + r*2304), src, 2304u, umb + buf*8);
        } else if (tid == 4){
            bulkcp(usb + (unsigned)(buf*BUFB), g_wTh + (size_t)s*3072, 12288u, umb + buf*8);
        }
    };

    float acc[2][7][4];
#pragma unroll
    for (int t = 0; t < 2; t++)
#pragma unroll
        for (int nt = 0; nt < 7; nt++)
#pragma unroll
            for (int j = 0; j < 4; j++) acc[t][nt][j] = 0.f;

    issue(0); issue(1); issue(2);
    for (int s = 0; s < 72; s++){
        if (s + 3 < 72) issue(s + 3);
        bwait(umb + (s&3)*8, (unsigned)((s >> 2) & 1));
        const char* buf = smem + (s&3)*BUFB;
        const uint4* wp = (const uint4*)buf;
        const unsigned* ibl = (const unsigned*)(buf + INBOFF) + (nw*8 + lr)*72 + lq;
#pragma unroll
        for (int kw = 0; kw < 3; kw++){
            uint4 A0 = wp[(kw*8 + mw*2    )*32 + lane];
            uint4 A1 = wp[(kw*8 + mw*2 + 1)*32 + lane];
#pragma unroll
            for (int nt = 0; nt < 7; nt++){
                unsigned b0 = ibl[nt*8 + kw];
                unsigned b1 = ibl[nt*8 + kw + 288];
                mma16f(acc[0][nt], A0, b0, b1);
                mma16f(acc[1][nt], A1, b0, b1);
            }
        }
        __syncthreads();
    }

    int h = h0 + nw;
#pragma unroll
    for (int t = 0; t < 2; t++){
        int o = (mw*2 + t)*16 + lq;
        float* base0 = g_x1c + ((size_t)(b*HIDc + o))*PP + (size_t)d*HW + h*56;
#pragma unroll
        for (int nt = 0; nt < 7; nt++){
            int w = nt*8 + 2*lr;
            float2 v0, v1;
            v0.x = fmaxf(acc[t][nt][0], 0.f); v0.y = fmaxf(acc[t][nt][1], 0.f);
            v1.x = fmaxf(acc[t][nt][2], 0.f); v1.y = fmaxf(acc[t][nt][3], 0.f);
            *(float2*)(base0 + w) = v0;
            *(float2*)(base0 + (size_t)8*PP + w) = v1;
        }
    }
}

// ---------------- K5: gate + proj_out via fp16 mma ----------------
#define FPAD 132
__global__ __launch_bounds__(256)
void k_final(float* __restrict__ out){
    __shared__ unsigned short sf[128*FPAD];
    int tid = threadIdx.x, lane = tid & 31, wid = tid >> 5;
    int lq = lane >> 2, lr = lane & 3;
    int mw = wid >> 2, nw = wid & 3;          // mw 0..1, nw 0..3
    int b = blockIdx.y;
    int p0 = blockIdx.x*128;
    for (int i = tid; i < 16384; i += 256){
        int c = i >> 7, p = i & 127;
        int gp = p0 + p;
        int d = gp / HW;
        float v = g_x1c[((size_t)(b*HIDc + c))*PP + gp] * g_gate[(b*HIDc + c)*DDim + d];
        sf[c*FPAD + p] = __half_as_ushort(__float2half_rn(v));
    }
    __syncthreads();
    float acc[2][4][4];
#pragma unroll
    for (int t = 0; t < 2; t++)
#pragma unroll
        for (int nt = 0; nt < 4; nt++)
#pragma unroll
            for (int j = 0; j < 4; j++) acc[t][nt][j] = 0.f;
    const uint4* gA = (const uint4*)g_fA;
#pragma unroll
    for (int ks = 0; ks < 8; ks++){
        uint4 A0 = gA[((mw*2    )*8 + ks)*32 + lane];
        uint4 A1 = gA[((mw*2 + 1)*8 + ks)*32 + lane];
#pragma unroll
        for (int nt = 0; nt < 4; nt++){
            int p = nw*32 + nt*8 + lq;
            int c0 = ks*16 + 2*lr;
            unsigned b0 = (unsigned)sf[c0*FPAD + p]       | ((unsigned)sf[(c0+1)*FPAD + p] << 16);
            unsigned b1 = (unsigned)sf[(c0+8)*FPAD + p]   | ((unsigned)sf[(c0+9)*FPAD + p] << 16);
            mma16f(acc[0][nt], A0, b0, b1);
            mma16f(acc[1][nt], A1, b0, b1);
        }
    }
#pragma unroll
    for (int t = 0; t < 2; t++){
        int o = mw*32 + t*16 + lq;
        float* base = out + ((size_t)(b*64 + o))*PP + p0 + nw*32 + 2*lr;
#pragma unroll
        for (int nt = 0; nt < 4; nt++){
            float2 v0, v1;
            v0.x = acc[t][nt][0]; v0.y = acc[t][nt][1];
            v1.x = acc[t][nt][2]; v1.y = acc[t][nt][3];
            *(float2*)(base + nt*8) = v0;
            *(float2*)(base + (size_t)8*PP + nt*8) = v1;
        }
    }
}

// ---------------- launch ----------------
extern "C" void kernel_launch(void* const* d_in, const int* in_sizes, int n_in,
                              void* d_out, int out_size){
    const float* inp      = (const float*)d_in[0];
    const float* W_in     = (const float*)d_in[1];
    const float* W_dw     = (const float*)d_in[2];
    const float* W_s      = (const float*)d_in[3];
    const float* W_t1     = (const float*)d_in[4];
    const float* W_t2     = (const float*)d_in[5];
    const float* m_in_w   = (const float*)d_in[6];
    const float* m_conv_w = (const float*)d_in[7];
    const float* m_conv_b = (const float*)d_in[8];
    const float* m_x_w    = (const float*)d_in[9];
    const float* m_dt_w   = (const float*)d_in[10];
    const float* m_dt_b   = (const float*)d_in[11];
    const float* m_A_log  = (const float*)d_in[12];
    const float* m_D      = (const float*)d_in[13];
    const float* m_out_w  = (const float*)d_in[14];
    const float* W_out    = (const float*)d_in[15];
    float* out = (float*)d_out;

    cudaFuncSetAttribute(k_projT, cudaFuncAttributeMaxDynamicSharedMemorySize, 51200);
    cudaFuncSetAttribute(k_m3,    cudaFuncAttributeMaxDynamicSharedMemorySize, 19712*4);
    cudaFuncSetAttribute(k_conv_mma, cudaFuncAttributeMaxDynamicSharedMemorySize, 4*BUFB);

    k_wpack   <<<912, 256>>>(W_s, W_in, W_out);                   // idx 0
    k_projT   <<<dim3(784, Bb), 512, 51200>>>(inp);               // idx 1
    k_dw      <<<Bb*C2, 256>>>(W_dw);                             // idx 2
    k_conv_mma<<<Bb*DDim*14, 512, 4*BUFB>>>();                    // idx 3 (profiled slot)
    k_m1      <<<32, 256>>>(W_t1);
    k_m2      <<<128, 256>>>(m_in_w);
    k_m3      <<<Bb, 256, 19712*4>>>(m_conv_w, m_conv_b, m_x_w, m_dt_w,
                                     m_dt_b, m_A_log, m_D);
    k_m4      <<<64, 128>>>(m_out_w, W_t2);
    k_final   <<<dim3(784, Bb), 256>>>(out);
}